// round 4
// baseline (speedup 1.0000x reference)
#include <cuda_runtime.h>

#define NN 50000
#define DD 128
#define EE 600000

// ---- scratch: sanctioned __device__ globals, statically addressed only ----
// g_buf[0] = H (x@W), g_buf[1] = A (aggregation), g_buf[2] = X (layer out)
__device__ __align__(256) float g_buf[3][NN * DD];
__device__ float g_deg[NN];
__device__ float g_dinv[NN];
__device__ int   g_row[EE];
__device__ int   g_col[EE];
__device__ float g_nrm[EE];
__device__ int   g_is64;

// ---------------- edge index dtype detection ----------------
// If the buffer really is int64, the first 64 values are all in [0, NN).
// If it's int32 (JAX x64 disabled), int64-reads pack two indices -> huge values.
__global__ void k_detect(const void* __restrict__ ei) {
    if (threadIdx.x != 0 || blockIdx.x != 0) return;
    const long long* p = (const long long*)ei;
    int ok = 1;
    for (int i = 0; i < 64; i++) {
        long long v = p[i];
        if (v < 0 || v >= NN) { ok = 0; break; }
    }
    g_is64 = ok;
}

// ---------------- edge prep ----------------
__global__ void k_deg_init() {
    int i = blockIdx.x * blockDim.x + threadIdx.x;
    if (i < NN) g_deg[i] = 1.0f;   // self loop
}

// decode indices (either dtype) -> int32, accumulate degree over col
__global__ void k_edge_prep(const void* __restrict__ ei) {
    int e = blockIdx.x * blockDim.x + threadIdx.x;
    if (e >= EE) return;
    int r, c;
    if (g_is64) {
        const long long* p = (const long long*)ei;
        r = (int)p[e];
        c = (int)p[EE + e];
    } else {
        const int* p = (const int*)ei;
        r = p[e];
        c = p[EE + e];
    }
    // clamp defensively (avoid crash even if detection were wrong)
    r = min(max(r, 0), NN - 1);
    c = min(max(c, 0), NN - 1);
    g_row[e] = r;
    g_col[e] = c;
    atomicAdd(&g_deg[c], 1.0f);
}

__global__ void k_dinv() {
    int i = blockIdx.x * blockDim.x + threadIdx.x;
    if (i < NN) g_dinv[i] = rsqrtf(g_deg[i]);
}

__global__ void k_norm() {
    int e = blockIdx.x * blockDim.x + threadIdx.x;
    if (e >= EE) return;
    g_nrm[e] = g_dinv[g_row[e]] * g_dinv[g_col[e]];
}

// ---------------- zero a scratch buffer ----------------
template <int DSTID>
__global__ void k_zero() {
    int i = blockIdx.x * blockDim.x + threadIdx.x;
    if (i >= NN * (DD / 4)) return;
    ((float4*)g_buf[DSTID])[i] = make_float4(0.f, 0.f, 0.f, 0.f);
}

// ---------------- SGEMM: C[M,128] = A[M,128] @ B[128,128] (+bias) ----------------
// BM=128, BN=128, BK=16, 256 threads, 8x8 per thread. SRCID/DSTID compile-time.
template <int SRCID, int DSTID, bool BIAS>
__global__ void __launch_bounds__(256) k_gemm(
    const float* __restrict__ Aext, const float* __restrict__ B,
    const float* __restrict__ bias, float* __restrict__ Cext, int M)
{
    const float* A = (SRCID < 0) ? Aext : (const float*)g_buf[SRCID];
    float* C = (DSTID < 0) ? Cext : (float*)g_buf[DSTID];

    __shared__ float As[16][128];   // [k][m]
    __shared__ float Bs[16][128];   // [k][n]

    const int tid = threadIdx.x;
    const int ty = tid >> 4;        // 0..15
    const int tx = tid & 15;        // 0..15
    const int rowBase = blockIdx.x * 128;

    float acc[8][8];
#pragma unroll
    for (int i = 0; i < 8; i++)
#pragma unroll
        for (int j = 0; j < 8; j++) acc[i][j] = 0.f;

    const int ar = tid >> 2;         // 0..63
    const int akg = (tid & 3) * 4;   // 0,4,8,12
    const int bkr = tid >> 5;        // 0..7
    const int bnc = (tid & 31) * 4;  // 0..124

    for (int kk = 0; kk < 128; kk += 16) {
#pragma unroll
        for (int h = 0; h < 2; h++) {
            int rr = ar + h * 64;
            int grow = rowBase + rr;
            float4 v = make_float4(0.f, 0.f, 0.f, 0.f);
            if (grow < M) v = *(const float4*)&A[(size_t)grow * DD + kk + akg];
            As[akg + 0][rr] = v.x;
            As[akg + 1][rr] = v.y;
            As[akg + 2][rr] = v.z;
            As[akg + 3][rr] = v.w;
        }
#pragma unroll
        for (int h = 0; h < 2; h++) {
            int kr = bkr + h * 8;
            *(float4*)&Bs[kr][bnc] = *(const float4*)&B[(size_t)(kk + kr) * DD + bnc];
        }
        __syncthreads();

#pragma unroll
        for (int k = 0; k < 16; k++) {
            float a[8], b[8];
#pragma unroll
            for (int i = 0; i < 8; i++) a[i] = As[k][ty * 8 + i];
#pragma unroll
            for (int j = 0; j < 8; j++) b[j] = Bs[k][tx * 8 + j];
#pragma unroll
            for (int i = 0; i < 8; i++)
#pragma unroll
                for (int j = 0; j < 8; j++) acc[i][j] += a[i] * b[j];
        }
        __syncthreads();
    }

#pragma unroll
    for (int i = 0; i < 8; i++) {
        int grow = rowBase + ty * 8 + i;
        if (grow >= M) continue;
#pragma unroll
        for (int j = 0; j < 8; j += 4) {
            int gcol = tx * 8 + j;
            float4 v = make_float4(acc[i][j], acc[i][j + 1], acc[i][j + 2], acc[i][j + 3]);
            if (BIAS) {
                v.x += bias[gcol + 0];
                v.y += bias[gcol + 1];
                v.z += bias[gcol + 2];
                v.w += bias[gcol + 3];
            }
            *(float4*)&C[(size_t)grow * DD + gcol] = v;
        }
    }
}

// ---------------- edge scatter: buf[DSTID][col] += H[row] * nrm ----------------
// One warp per edge; lane covers 4 columns (float4 gather, 4 atomic adds).
template <int DSTID>
__global__ void __launch_bounds__(256) k_scatter()
{
    int w = (blockIdx.x * blockDim.x + threadIdx.x) >> 5;
    if (w >= EE) return;
    int lane = threadIdx.x & 31;
    int r = g_row[w];
    int c = g_col[w];
    float nrm = g_nrm[w];
    float4 h = *(const float4*)&g_buf[0][(size_t)r * DD + lane * 4];
    size_t base = (size_t)c * DD + lane * 4;
    atomicAdd(&g_buf[DSTID][base + 0], h.x * nrm);
    atomicAdd(&g_buf[DSTID][base + 1], h.y * nrm);
    atomicAdd(&g_buf[DSTID][base + 2], h.z * nrm);
    atomicAdd(&g_buf[DSTID][base + 3], h.w * nrm);
}

// ---------------- epilogue: buf[XID] = (buf[AID] + H*dinv^2), optional ReLU ----------------
template <int AID, int XID, bool RELU>
__global__ void k_finish()
{
    int idx = blockIdx.x * blockDim.x + threadIdx.x;   // over NN*32 float4s
    if (idx >= NN * (DD / 4)) return;
    int node = idx >> 5;
    float d = g_dinv[node];
    float d2 = d * d;
    float4 a = ((const float4*)g_buf[AID])[idx];
    float4 h = ((const float4*)g_buf[0])[idx];
    float4 v;
    v.x = a.x + h.x * d2;
    v.y = a.y + h.y * d2;
    v.z = a.z + h.z * d2;
    v.w = a.w + h.w * d2;
    if (RELU) {
        v.x = fmaxf(v.x, 0.f);
        v.y = fmaxf(v.y, 0.f);
        v.z = fmaxf(v.z, 0.f);
        v.w = fmaxf(v.w, 0.f);
    }
    ((float4*)g_buf[XID])[idx] = v;
}

extern "C" void kernel_launch(void* const* d_in, const int* in_sizes, int n_in,
                              void* d_out, int out_size)
{
    const float* x  = (const float*)d_in[0];
    const void*  ei = d_in[1];
    const float* W1 = (const float*)d_in[2];
    const float* R1 = (const float*)d_in[3];
    const float* W2 = (const float*)d_in[4];
    const float* R2 = (const float*)d_in[5];
    const float* W3 = (const float*)d_in[6];
    const float* Wh = (const float*)d_in[7];
    const float* bh = (const float*)d_in[8];
    float* out = (float*)d_out;

    const int GEMM_GRID = (NN + 127) / 128;
    const int VEC_GRID  = (NN * (DD / 4) + 255) / 256;
    const int SC_GRID   = (EE * 32 + 255) / 256;
    const int E_GRID    = (EE + 255) / 256;
    const int N_GRID    = (NN + 255) / 256;

    // edge prep: dtype detect, degrees, norms, int32 indices
    k_detect<<<1, 32>>>(ei);
    k_deg_init<<<N_GRID, 256>>>();
    k_edge_prep<<<E_GRID, 256>>>(ei);
    k_dinv<<<N_GRID, 256>>>();
    k_norm<<<E_GRID, 256>>>();

    // ---- layer 1: x -> buf2 (residual + relu) ----
    k_gemm<-1, 0, false><<<GEMM_GRID, 256>>>(x, W1, nullptr, nullptr, NN); // H = x@W1
    k_gemm<-1, 1, false><<<GEMM_GRID, 256>>>(x, R1, nullptr, nullptr, NN); // A = x@R1
    k_scatter<1><<<SC_GRID, 256>>>();                                      // A += scatter(H)
    k_finish<1, 2, true><<<VEC_GRID, 256>>>();                             // X = relu(A + H*d2)

    // ---- layer 2: buf2 -> buf1 (residual + relu) ----
    k_gemm<2, 0, false><<<GEMM_GRID, 256>>>(nullptr, W2, nullptr, nullptr, NN); // H = X@W2
    k_gemm<2, 1, false><<<GEMM_GRID, 256>>>(nullptr, R2, nullptr, nullptr, NN); // A = X@R2
    k_scatter<1><<<SC_GRID, 256>>>();                                           // A += scatter(H)
    k_finish<1, 1, true><<<VEC_GRID, 256>>>();                                  // A = relu(A + H*d2)

    // ---- layer 3: buf1 -> buf2 (no residual, no act) ----
    k_gemm<1, 0, false><<<GEMM_GRID, 256>>>(nullptr, W3, nullptr, nullptr, NN); // H = A@W3
    k_zero<2><<<VEC_GRID, 256>>>();                                             // X = 0
    k_scatter<2><<<SC_GRID, 256>>>();                                           // X += scatter(H)
    k_finish<2, 2, false><<<VEC_GRID, 256>>>();                                 // X = X + H*d2

    // ---- head: out = X @ Wh + bh ----
    k_gemm<2, -1, true><<<GEMM_GRID, 256>>>(nullptr, Wh, bh, out, NN);
}

// round 6
// speedup vs baseline: 1.0163x; 1.0163x over previous
#include <cuda_runtime.h>
#include <cstdint>

#define NN 50000
#define DD 128
#define EE 600000

// ---- scratch: sanctioned __device__ globals, statically addressed only ----
// g_buf[0] = H (x@W), g_buf[1] = A (aggregation), g_buf[2] = X (layer out)
__device__ __align__(256) float g_buf[3][NN * DD];
__device__ float g_deg[NN];
__device__ float g_dinv[NN];
__device__ int   g_row[EE];
__device__ int   g_col[EE];
__device__ float g_nrm[EE];
__device__ int   g_is64;

// ---------------- edge index dtype detection ----------------
__global__ void k_detect(const void* __restrict__ ei) {
    if (threadIdx.x != 0 || blockIdx.x != 0) return;
    const long long* p = (const long long*)ei;
    int ok = 1;
    for (int i = 0; i < 64; i++) {
        long long v = p[i];
        if (v < 0 || v >= NN) { ok = 0; break; }
    }
    g_is64 = ok;
}

// ---------------- edge prep ----------------
__global__ void k_deg_init() {
    int i = blockIdx.x * blockDim.x + threadIdx.x;
    if (i < NN) g_deg[i] = 1.0f;   // self loop
}

__global__ void k_edge_prep(const void* __restrict__ ei) {
    int e = blockIdx.x * blockDim.x + threadIdx.x;
    if (e >= EE) return;
    int r, c;
    if (g_is64) {
        const long long* p = (const long long*)ei;
        r = (int)p[e];
        c = (int)p[EE + e];
    } else {
        const int* p = (const int*)ei;
        r = p[e];
        c = p[EE + e];
    }
    r = min(max(r, 0), NN - 1);
    c = min(max(c, 0), NN - 1);
    g_row[e] = r;
    g_col[e] = c;
    atomicAdd(&g_deg[c], 1.0f);
}

__global__ void k_dinv() {
    int i = blockIdx.x * blockDim.x + threadIdx.x;
    if (i < NN) g_dinv[i] = rsqrtf(g_deg[i]);
}

__global__ void k_norm() {
    int e = blockIdx.x * blockDim.x + threadIdx.x;
    if (e >= EE) return;
    g_nrm[e] = g_dinv[g_row[e]] * g_dinv[g_col[e]];
}

// ---------------- zero a scratch buffer ----------------
template <int DSTID>
__global__ void k_zero() {
    int i = blockIdx.x * blockDim.x + threadIdx.x;
    if (i >= NN * (DD / 4)) return;
    ((float4*)g_buf[DSTID])[i] = make_float4(0.f, 0.f, 0.f, 0.f);
}

// ---------------- TF32 helpers ----------------
__device__ __forceinline__ uint32_t f2tf32(float f) {
    uint32_t u;
    asm("cvt.rna.tf32.f32 %0, %1;" : "=r"(u) : "f"(f));
    return u;
}

// ---------------- TF32 MMA GEMM: C[M,128] = A[M,128] @ B[128,128] (+bias) ----------------
// Block tile 128x128, 8 warps (2m x 4n), warp tile 64x32, K chunks of 32.
// m16n8k8 tf32 mma; fragments via ldmatrix from tf32-staged smem.
template <int SRCID, int DSTID, bool BIAS>
__global__ void __launch_bounds__(256, 2) k_gemm(
    const float* __restrict__ Aext, const float* __restrict__ B,
    const float* __restrict__ bias, float* __restrict__ Cext, int M)
{
    const float* A = (SRCID < 0) ? Aext : (const float*)g_buf[SRCID];
    float* C = (DSTID < 0) ? Cext : (float*)g_buf[DSTID];

    __shared__ uint32_t As[128][40];   // [m][k-chunk], pitch 40 (16B-aligned rows)
    __shared__ uint32_t Bt[128][40];   // [n][k-chunk] (transposed B)

    const int tid = threadIdx.x;
    const int lane = tid & 31;
    const int wid = tid >> 5;
    const int warpM = wid >> 2;        // 0..1
    const int warpN = wid & 3;         // 0..3
    const int rowBase = blockIdx.x * 128;

    float acc[4][4][4];
#pragma unroll
    for (int mt = 0; mt < 4; mt++)
#pragma unroll
        for (int nt = 0; nt < 4; nt++)
#pragma unroll
            for (int i = 0; i < 4; i++) acc[mt][nt][i] = 0.f;

    // ldmatrix per-lane addresses (byte offsets into shared)
    uint32_t aAddr[4], bAddr[4];
    {
        int ar = warpM * 64 + ((lane >> 3) & 1) * 8 + (lane & 7);
        int ac = ((lane >> 4) & 1) * 4;
#pragma unroll
        for (int mt = 0; mt < 4; mt++)
            aAddr[mt] = (uint32_t)__cvta_generic_to_shared(&As[ar + mt * 16][ac]);
        int br = warpN * 32 + (lane & 7);
        int bc = ((lane >> 3) & 1) * 4;
#pragma unroll
        for (int nt = 0; nt < 4; nt++)
            bAddr[nt] = (uint32_t)__cvta_generic_to_shared(&Bt[br + nt * 8][bc]);
    }

    for (int kc0 = 0; kc0 < 128; kc0 += 32) {
        // stage A chunk: 128 rows x 32 cols, tf32-converted
#pragma unroll
        for (int i = 0; i < 4; i++) {
            int lin = tid + i * 256;           // 0..1023
            int row = lin >> 3;
            int c4 = (lin & 7) * 4;
            int grow = min(rowBase + row, M - 1);
            float4 v = *(const float4*)&A[(size_t)grow * DD + kc0 + c4];
            *(uint4*)&As[row][c4] = make_uint4(f2tf32(v.x), f2tf32(v.y), f2tf32(v.z), f2tf32(v.w));
        }
        // stage B chunk transposed: Bt[n][k]
#pragma unroll
        for (int i = 0; i < 4; i++) {
            int lin = tid + i * 256;           // 0..1023
            int kr = lin >> 5;                 // 0..31
            int n4 = (lin & 31) * 4;           // 0..124
            float4 v = *(const float4*)&B[(size_t)(kc0 + kr) * DD + n4];
            Bt[n4 + 0][kr] = f2tf32(v.x);
            Bt[n4 + 1][kr] = f2tf32(v.y);
            Bt[n4 + 2][kr] = f2tf32(v.z);
            Bt[n4 + 3][kr] = f2tf32(v.w);
        }
        __syncthreads();

#pragma unroll
        for (int ks = 0; ks < 4; ks++) {
            uint32_t a[4][4], b[4][2];
#pragma unroll
            for (int nt = 0; nt < 4; nt++) {
                asm volatile("ldmatrix.sync.aligned.m8n8.x2.shared.b16 {%0,%1}, [%2];"
                             : "=r"(b[nt][0]), "=r"(b[nt][1])
                             : "r"(bAddr[nt] + ks * 32));
            }
#pragma unroll
            for (int mt = 0; mt < 4; mt++) {
                asm volatile("ldmatrix.sync.aligned.m8n8.x4.shared.b16 {%0,%1,%2,%3}, [%4];"
                             : "=r"(a[mt][0]), "=r"(a[mt][1]), "=r"(a[mt][2]), "=r"(a[mt][3])
                             : "r"(aAddr[mt] + ks * 32));
            }
#pragma unroll
            for (int mt = 0; mt < 4; mt++)
#pragma unroll
                for (int nt = 0; nt < 4; nt++) {
                    asm volatile(
                        "mma.sync.aligned.m16n8k8.row.col.f32.tf32.tf32.f32 "
                        "{%0,%1,%2,%3}, {%4,%5,%6,%7}, {%8,%9}, {%0,%1,%2,%3};"
                        : "+f"(acc[mt][nt][0]), "+f"(acc[mt][nt][1]),
                          "+f"(acc[mt][nt][2]), "+f"(acc[mt][nt][3])
                        : "r"(a[mt][0]), "r"(a[mt][1]), "r"(a[mt][2]), "r"(a[mt][3]),
                          "r"(b[nt][0]), "r"(b[nt][1]));
                }
        }
        __syncthreads();
    }

    // epilogue
    const int g = lane >> 2;
    const int t = lane & 3;
#pragma unroll
    for (int mt = 0; mt < 4; mt++) {
        int r0 = rowBase + warpM * 64 + mt * 16 + g;
#pragma unroll
        for (int nt = 0; nt < 4; nt++) {
            int col = warpN * 32 + nt * 8 + t * 2;
            float2 v0 = make_float2(acc[mt][nt][0], acc[mt][nt][1]);
            float2 v1 = make_float2(acc[mt][nt][2], acc[mt][nt][3]);
            if (BIAS) {
                float2 bv = *(const float2*)&bias[col];
                v0.x += bv.x; v0.y += bv.y;
                v1.x += bv.x; v1.y += bv.y;
            }
            if (r0 < M)     *(float2*)&C[(size_t)r0 * DD + col] = v0;
            if (r0 + 8 < M) *(float2*)&C[(size_t)(r0 + 8) * DD + col] = v1;
        }
    }
}

// ---------------- edge scatter: buf[DSTID][col] += H[row] * nrm ----------------
template <int DSTID>
__global__ void __launch_bounds__(256) k_scatter()
{
    int w = (blockIdx.x * blockDim.x + threadIdx.x) >> 5;
    if (w >= EE) return;
    int lane = threadIdx.x & 31;
    int r = g_row[w];
    int c = g_col[w];
    float nrm = g_nrm[w];
    float4 h = *(const float4*)&g_buf[0][(size_t)r * DD + lane * 4];
    size_t base = (size_t)c * DD + lane * 4;
    atomicAdd(&g_buf[DSTID][base + 0], h.x * nrm);
    atomicAdd(&g_buf[DSTID][base + 1], h.y * nrm);
    atomicAdd(&g_buf[DSTID][base + 2], h.z * nrm);
    atomicAdd(&g_buf[DSTID][base + 3], h.w * nrm);
}

// ---------------- epilogue: buf[XID] = (buf[AID] + H*dinv^2), optional ReLU ----------------
template <int AID, int XID, bool RELU>
__global__ void k_finish()
{
    int idx = blockIdx.x * blockDim.x + threadIdx.x;   // over NN*32 float4s
    if (idx >= NN * (DD / 4)) return;
    int node = idx >> 5;
    float d = g_dinv[node];
    float d2 = d * d;
    float4 a = ((const float4*)g_buf[AID])[idx];
    float4 h = ((const float4*)g_buf[0])[idx];
    float4 v;
    v.x = a.x + h.x * d2;
    v.y = a.y + h.y * d2;
    v.z = a.z + h.z * d2;
    v.w = a.w + h.w * d2;
    if (RELU) {
        v.x = fmaxf(v.x, 0.f);
        v.y = fmaxf(v.y, 0.f);
        v.z = fmaxf(v.z, 0.f);
        v.w = fmaxf(v.w, 0.f);
    }
    ((float4*)g_buf[XID])[idx] = v;
}

extern "C" void kernel_launch(void* const* d_in, const int* in_sizes, int n_in,
                              void* d_out, int out_size)
{
    const float* x  = (const float*)d_in[0];
    const void*  ei = d_in[1];
    const float* W1 = (const float*)d_in[2];
    const float* R1 = (const float*)d_in[3];
    const float* W2 = (const float*)d_in[4];
    const float* R2 = (const float*)d_in[5];
    const float* W3 = (const float*)d_in[6];
    const float* Wh = (const float*)d_in[7];
    const float* bh = (const float*)d_in[8];
    float* out = (float*)d_out;

    const int GEMM_GRID = (NN + 127) / 128;
    const int VEC_GRID  = (NN * (DD / 4) + 255) / 256;
    const int SC_GRID   = (EE * 32 + 255) / 256;
    const int E_GRID    = (EE + 255) / 256;
    const int N_GRID    = (NN + 255) / 256;

    // edge prep: dtype detect, degrees, norms, int32 indices
    k_detect<<<1, 32>>>(ei);
    k_deg_init<<<N_GRID, 256>>>();
    k_edge_prep<<<E_GRID, 256>>>(ei);
    k_dinv<<<N_GRID, 256>>>();
    k_norm<<<E_GRID, 256>>>();

    // ---- layer 1: x -> buf2 (residual + relu) ----
    k_gemm<-1, 0, false><<<GEMM_GRID, 256>>>(x, W1, nullptr, nullptr, NN); // H = x@W1
    k_gemm<-1, 1, false><<<GEMM_GRID, 256>>>(x, R1, nullptr, nullptr, NN); // A = x@R1
    k_scatter<1><<<SC_GRID, 256>>>();                                      // A += scatter(H)
    k_finish<1, 2, true><<<VEC_GRID, 256>>>();                             // X = relu(A + H*d2)

    // ---- layer 2: buf2 -> buf1 (residual + relu) ----
    k_gemm<2, 0, false><<<GEMM_GRID, 256>>>(nullptr, W2, nullptr, nullptr, NN); // H = X@W2
    k_gemm<2, 1, false><<<GEMM_GRID, 256>>>(nullptr, R2, nullptr, nullptr, NN); // A = X@R2
    k_scatter<1><<<SC_GRID, 256>>>();                                           // A += scatter(H)
    k_finish<1, 1, true><<<VEC_GRID, 256>>>();                                  // A = relu(A + H*d2)

    // ---- layer 3: buf1 -> buf2 (no residual, no act) ----
    k_gemm<1, 0, false><<<GEMM_GRID, 256>>>(nullptr, W3, nullptr, nullptr, NN); // H = A@W3
    k_zero<2><<<VEC_GRID, 256>>>();                                             // X = 0
    k_scatter<2><<<SC_GRID, 256>>>();                                           // X += scatter(H)
    k_finish<2, 2, false><<<VEC_GRID, 256>>>();                                 // X = X + H*d2

    // ---- head: out = X @ Wh + bh ----
    k_gemm<2, -1, true><<<GEMM_GRID, 256>>>(nullptr, Wh, bh, out, NN);
}

// round 7
// speedup vs baseline: 2.0500x; 2.0170x over previous
#include <cuda_runtime.h>
#include <cstdint>

#define NN 50000
#define DD 128
#define EE 600000
#define NBLK 196   // ceil(NN/256)

// ---- scratch: sanctioned __device__ globals, statically addressed only ----
// g_buf[0] = H (x@W), g_buf[1] = A/residual, g_buf[2] = X (layer out)
__device__ __align__(256) float g_buf[3][NN * DD];
__device__ float g_dinv[NN];
__device__ int   g_row[EE];
__device__ int   g_col[EE];
__device__ int   g_cnt[NN];
__device__ int   g_off[NN];
__device__ int   g_cursor[NN];
__device__ int   g_bsum[NBLK];
__device__ int   g_boff[NBLK];
__device__ int   g_csr_row[EE];
__device__ float g_csr_nrm[EE];
__device__ int   g_is64;

// ---------------- edge index dtype detection ----------------
__global__ void k_detect(const void* __restrict__ ei) {
    if (threadIdx.x != 0 || blockIdx.x != 0) return;
    const long long* p = (const long long*)ei;
    int ok = 1;
    for (int i = 0; i < 64; i++) {
        long long v = p[i];
        if (v < 0 || v >= NN) { ok = 0; break; }
    }
    g_is64 = ok;
}

// ---------------- CSR construction ----------------
__global__ void k_cnt_init() {
    int i = blockIdx.x * blockDim.x + threadIdx.x;
    if (i < NN) g_cnt[i] = 0;
}

__global__ void k_count(const void* __restrict__ ei) {
    int e = blockIdx.x * blockDim.x + threadIdx.x;
    if (e >= EE) return;
    int r, c;
    if (g_is64) {
        const long long* p = (const long long*)ei;
        r = (int)p[e];
        c = (int)p[EE + e];
    } else {
        const int* p = (const int*)ei;
        r = p[e];
        c = p[EE + e];
    }
    r = min(max(r, 0), NN - 1);
    c = min(max(c, 0), NN - 1);
    g_row[e] = r;
    g_col[e] = c;
    atomicAdd(&g_cnt[c], 1);
}

__global__ void k_dinv() {
    int i = blockIdx.x * blockDim.x + threadIdx.x;
    if (i < NN) g_dinv[i] = rsqrtf((float)g_cnt[i] + 1.0f);  // +1 self loop
}

// 256-thread exclusive block scan; returns exclusive prefix, sets *bsum to block total
__device__ __forceinline__ int blockScanEx(int v, int* bsum) {
    int lane = threadIdx.x & 31, wid = threadIdx.x >> 5;
    int x = v;
#pragma unroll
    for (int d = 1; d < 32; d <<= 1) {
        int y = __shfl_up_sync(0xffffffffu, x, d);
        if (lane >= d) x += y;
    }
    __shared__ int wsum[8];
    if (lane == 31) wsum[wid] = x;
    __syncthreads();
    if (wid == 0) {
        int t = (lane < 8) ? wsum[lane] : 0;
#pragma unroll
        for (int d = 1; d < 8; d <<= 1) {
            int y = __shfl_up_sync(0xffffffffu, t, d);
            if (lane >= d) t += y;
        }
        if (lane < 8) wsum[lane] = t;
    }
    __syncthreads();
    int incl = x + (wid > 0 ? wsum[wid - 1] : 0);
    *bsum = wsum[7];
    return incl - v;
}

__global__ void k_scan1() {
    int i = blockIdx.x * 256 + threadIdx.x;
    int v = (i < NN) ? g_cnt[i] : 0;
    int bsum;
    int ex = blockScanEx(v, &bsum);
    if (i < NN) g_off[i] = ex;
    if (threadIdx.x == 0) g_bsum[blockIdx.x] = bsum;
}

__global__ void k_scan2() {
    int i = threadIdx.x;
    int v = (i < NBLK) ? g_bsum[i] : 0;
    int bsum;
    int ex = blockScanEx(v, &bsum);
    if (i < NBLK) g_boff[i] = ex;
}

__global__ void k_scan3() {
    int i = blockIdx.x * 256 + threadIdx.x;
    if (i >= NN) return;
    int o = g_off[i] + g_boff[blockIdx.x];
    g_off[i] = o;
    g_cursor[i] = o;
}

__global__ void k_fill() {
    int e = blockIdx.x * blockDim.x + threadIdx.x;
    if (e >= EE) return;
    int r = g_row[e];
    int c = g_col[e];
    int pos = atomicAdd(&g_cursor[c], 1);
    g_csr_row[pos] = r;
    g_csr_nrm[pos] = g_dinv[r] * g_dinv[c];
}

// ---------------- TF32 helpers ----------------
__device__ __forceinline__ uint32_t f2tf32(float f) {
    uint32_t u;
    asm("cvt.rna.tf32.f32 %0, %1;" : "=r"(u) : "f"(f));
    return u;
}

// ---------------- TF32 MMA GEMM: C[M,128] = A[M,128] @ B[128,128] (+bias) ----------------
template <int SRCID, int DSTID, bool BIAS>
__global__ void __launch_bounds__(256, 2) k_gemm(
    const float* __restrict__ Aext, const float* __restrict__ B,
    const float* __restrict__ bias, float* __restrict__ Cext, int M)
{
    const float* A = (SRCID < 0) ? Aext : (const float*)g_buf[SRCID];
    float* C = (DSTID < 0) ? Cext : (float*)g_buf[DSTID];

    __shared__ uint32_t As[128][40];
    __shared__ uint32_t Bt[128][40];

    const int tid = threadIdx.x;
    const int lane = tid & 31;
    const int wid = tid >> 5;
    const int warpM = wid >> 2;
    const int warpN = wid & 3;
    const int rowBase = blockIdx.x * 128;

    float acc[4][4][4];
#pragma unroll
    for (int mt = 0; mt < 4; mt++)
#pragma unroll
        for (int nt = 0; nt < 4; nt++)
#pragma unroll
            for (int i = 0; i < 4; i++) acc[mt][nt][i] = 0.f;

    uint32_t aAddr[4], bAddr[4];
    {
        int ar = warpM * 64 + ((lane >> 3) & 1) * 8 + (lane & 7);
        int ac = ((lane >> 4) & 1) * 4;
#pragma unroll
        for (int mt = 0; mt < 4; mt++)
            aAddr[mt] = (uint32_t)__cvta_generic_to_shared(&As[ar + mt * 16][ac]);
        int br = warpN * 32 + (lane & 7);
        int bc = ((lane >> 3) & 1) * 4;
#pragma unroll
        for (int nt = 0; nt < 4; nt++)
            bAddr[nt] = (uint32_t)__cvta_generic_to_shared(&Bt[br + nt * 8][bc]);
    }

    for (int kc0 = 0; kc0 < 128; kc0 += 32) {
#pragma unroll
        for (int i = 0; i < 4; i++) {
            int lin = tid + i * 256;
            int row = lin >> 3;
            int c4 = (lin & 7) * 4;
            int grow = min(rowBase + row, M - 1);
            float4 v = *(const float4*)&A[(size_t)grow * DD + kc0 + c4];
            *(uint4*)&As[row][c4] = make_uint4(f2tf32(v.x), f2tf32(v.y), f2tf32(v.z), f2tf32(v.w));
        }
#pragma unroll
        for (int i = 0; i < 4; i++) {
            int lin = tid + i * 256;
            int kr = lin >> 5;
            int n4 = (lin & 31) * 4;
            float4 v = *(const float4*)&B[(size_t)(kc0 + kr) * DD + n4];
            Bt[n4 + 0][kr] = f2tf32(v.x);
            Bt[n4 + 1][kr] = f2tf32(v.y);
            Bt[n4 + 2][kr] = f2tf32(v.z);
            Bt[n4 + 3][kr] = f2tf32(v.w);
        }
        __syncthreads();

#pragma unroll
        for (int ks = 0; ks < 4; ks++) {
            uint32_t a[4][4], b[4][2];
#pragma unroll
            for (int nt = 0; nt < 4; nt++) {
                asm volatile("ldmatrix.sync.aligned.m8n8.x2.shared.b16 {%0,%1}, [%2];"
                             : "=r"(b[nt][0]), "=r"(b[nt][1])
                             : "r"(bAddr[nt] + ks * 32));
            }
#pragma unroll
            for (int mt = 0; mt < 4; mt++) {
                asm volatile("ldmatrix.sync.aligned.m8n8.x4.shared.b16 {%0,%1,%2,%3}, [%4];"
                             : "=r"(a[mt][0]), "=r"(a[mt][1]), "=r"(a[mt][2]), "=r"(a[mt][3])
                             : "r"(aAddr[mt] + ks * 32));
            }
#pragma unroll
            for (int mt = 0; mt < 4; mt++)
#pragma unroll
                for (int nt = 0; nt < 4; nt++) {
                    asm volatile(
                        "mma.sync.aligned.m16n8k8.row.col.f32.tf32.tf32.f32 "
                        "{%0,%1,%2,%3}, {%4,%5,%6,%7}, {%8,%9}, {%0,%1,%2,%3};"
                        : "+f"(acc[mt][nt][0]), "+f"(acc[mt][nt][1]),
                          "+f"(acc[mt][nt][2]), "+f"(acc[mt][nt][3])
                        : "r"(a[mt][0]), "r"(a[mt][1]), "r"(a[mt][2]), "r"(a[mt][3]),
                          "r"(b[nt][0]), "r"(b[nt][1]));
                }
        }
        __syncthreads();
    }

    const int g = lane >> 2;
    const int t = lane & 3;
#pragma unroll
    for (int mt = 0; mt < 4; mt++) {
        int r0 = rowBase + warpM * 64 + mt * 16 + g;
#pragma unroll
        for (int nt = 0; nt < 4; nt++) {
            int col = warpN * 32 + nt * 8 + t * 2;
            float2 v0 = make_float2(acc[mt][nt][0], acc[mt][nt][1]);
            float2 v1 = make_float2(acc[mt][nt][2], acc[mt][nt][3]);
            if (BIAS) {
                float2 bv = *(const float2*)&bias[col];
                v0.x += bv.x; v0.y += bv.y;
                v1.x += bv.x; v1.y += bv.y;
            }
            if (r0 < M)     *(float2*)&C[(size_t)r0 * DD + col] = v0;
            if (r0 + 8 < M) *(float2*)&C[(size_t)(r0 + 8) * DD + col] = v1;
        }
    }
}

// ---------------- CSR gather-aggregate (fused self-loop + residual + relu) ----------------
// One warp per node; lane covers 4 columns (float4). No atomics.
// dst[node] = sum_in-edges H[row]*nrm + H[node]*dinv^2 (+ buf[RESID]) (relu?)
template <int RESID, int DSTID, bool RELU>
__global__ void __launch_bounds__(256) k_aggregate()
{
    int node = (blockIdx.x * blockDim.x + threadIdx.x) >> 5;
    if (node >= NN) return;
    int lane = threadIdx.x & 31;

    const float4* H4 = (const float4*)g_buf[0];
    float4 acc = make_float4(0.f, 0.f, 0.f, 0.f);

    int s = g_off[node];
    int end = s + g_cnt[node];

    int j = s;
    for (; j + 2 <= end; j += 2) {
        int r0 = g_csr_row[j];
        int r1 = g_csr_row[j + 1];
        float w0 = g_csr_nrm[j];
        float w1 = g_csr_nrm[j + 1];
        float4 h0 = H4[r0 * 32 + lane];
        float4 h1 = H4[r1 * 32 + lane];
        acc.x += h0.x * w0 + h1.x * w1;
        acc.y += h0.y * w0 + h1.y * w1;
        acc.z += h0.z * w0 + h1.z * w1;
        acc.w += h0.w * w0 + h1.w * w1;
    }
    if (j < end) {
        int r0 = g_csr_row[j];
        float w0 = g_csr_nrm[j];
        float4 h0 = H4[r0 * 32 + lane];
        acc.x += h0.x * w0;
        acc.y += h0.y * w0;
        acc.z += h0.z * w0;
        acc.w += h0.w * w0;
    }

    // self loop
    float d = g_dinv[node];
    float d2 = d * d;
    float4 hs = H4[node * 32 + lane];
    acc.x += hs.x * d2;
    acc.y += hs.y * d2;
    acc.z += hs.z * d2;
    acc.w += hs.w * d2;

    if (RESID >= 0) {
        float4 rv = ((const float4*)g_buf[RESID])[node * 32 + lane];
        acc.x += rv.x; acc.y += rv.y; acc.z += rv.z; acc.w += rv.w;
    }
    if (RELU) {
        acc.x = fmaxf(acc.x, 0.f);
        acc.y = fmaxf(acc.y, 0.f);
        acc.z = fmaxf(acc.z, 0.f);
        acc.w = fmaxf(acc.w, 0.f);
    }
    ((float4*)g_buf[DSTID])[node * 32 + lane] = acc;
}

extern "C" void kernel_launch(void* const* d_in, const int* in_sizes, int n_in,
                              void* d_out, int out_size)
{
    const float* x  = (const float*)d_in[0];
    const void*  ei = d_in[1];
    const float* W1 = (const float*)d_in[2];
    const float* R1 = (const float*)d_in[3];
    const float* W2 = (const float*)d_in[4];
    const float* R2 = (const float*)d_in[5];
    const float* W3 = (const float*)d_in[6];
    const float* Wh = (const float*)d_in[7];
    const float* bh = (const float*)d_in[8];
    float* out = (float*)d_out;

    const int GEMM_GRID = (NN + 127) / 128;
    const int AGG_GRID  = (NN * 32 + 255) / 256;
    const int E_GRID    = (EE + 255) / 256;
    const int N_GRID    = (NN + 255) / 256;

    // ---- CSR prep ----
    k_detect<<<1, 32>>>(ei);
    k_cnt_init<<<N_GRID, 256>>>();
    k_count<<<E_GRID, 256>>>(ei);
    k_dinv<<<N_GRID, 256>>>();
    k_scan1<<<NBLK, 256>>>();
    k_scan2<<<1, 256>>>();
    k_scan3<<<NBLK, 256>>>();
    k_fill<<<E_GRID, 256>>>();

    // ---- layer 1: x -> buf2 (residual + relu) ----
    k_gemm<-1, 0, false><<<GEMM_GRID, 256>>>(x, W1, nullptr, nullptr, NN);  // H = x@W1
    k_gemm<-1, 1, false><<<GEMM_GRID, 256>>>(x, R1, nullptr, nullptr, NN);  // res = x@R1
    k_aggregate<1, 2, true><<<AGG_GRID, 256>>>();                           // X = relu(agg + res)

    // ---- layer 2: buf2 -> buf2 (residual + relu) ----
    k_gemm<2, 0, false><<<GEMM_GRID, 256>>>(nullptr, W2, nullptr, nullptr, NN); // H = X@W2
    k_gemm<2, 1, false><<<GEMM_GRID, 256>>>(nullptr, R2, nullptr, nullptr, NN); // res = X@R2
    k_aggregate<1, 2, true><<<AGG_GRID, 256>>>();                               // X = relu(agg + res)

    // ---- layer 3: buf2 -> buf1 (no residual, no act) ----
    k_gemm<2, 0, false><<<GEMM_GRID, 256>>>(nullptr, W3, nullptr, nullptr, NN); // H = X@W3
    k_aggregate<-1, 1, false><<<AGG_GRID, 256>>>();                             // buf1 = agg

    // ---- head: out = buf1 @ Wh + bh ----
    k_gemm<1, -1, true><<<GEMM_GRID, 256>>>(nullptr, Wh, bh, out, NN);
}

// round 10
// speedup vs baseline: 2.4490x; 1.1946x over previous
#include <cuda_runtime.h>
#include <cstdint>

#define NN 50000
#define DD 128
#define EE 600000
#define NBLK 196   // ceil(NN/256)

// ---- scratch: sanctioned __device__ globals, statically addressed only ----
// g_buf[0] = H (x@W), g_buf[1] = A/residual, g_buf[2] = X (layer out)
__device__ __align__(256) float g_buf[3][NN * DD];
__device__ float g_dinv[NN];
__device__ int   g_row[EE];
__device__ int   g_col[EE];
__device__ int   g_cnt[NN];
__device__ int   g_off[NN];
__device__ int   g_cursor[NN];
__device__ int   g_bsum[NBLK];
__device__ int   g_boff[NBLK];
__device__ int   g_csr_row[EE];
__device__ float g_csr_nrm[EE];
__device__ int   g_is64;

// ---------------- edge index dtype detection ----------------
__global__ void k_detect(const void* __restrict__ ei) {
    if (threadIdx.x != 0 || blockIdx.x != 0) return;
    const long long* p = (const long long*)ei;
    int ok = 1;
    for (int i = 0; i < 64; i++) {
        long long v = p[i];
        if (v < 0 || v >= NN) { ok = 0; break; }
    }
    g_is64 = ok;
}

// ---------------- CSR construction ----------------
__global__ void k_cnt_init() {
    int i = blockIdx.x * blockDim.x + threadIdx.x;
    if (i < NN) g_cnt[i] = 0;
}

__global__ void k_count(const void* __restrict__ ei) {
    int e = blockIdx.x * blockDim.x + threadIdx.x;
    if (e >= EE) return;
    int r, c;
    if (g_is64) {
        const long long* p = (const long long*)ei;
        r = (int)p[e];
        c = (int)p[EE + e];
    } else {
        const int* p = (const int*)ei;
        r = p[e];
        c = p[EE + e];
    }
    r = min(max(r, 0), NN - 1);
    c = min(max(c, 0), NN - 1);
    g_row[e] = r;
    g_col[e] = c;
    atomicAdd(&g_cnt[c], 1);
}

__global__ void k_dinv() {
    int i = blockIdx.x * blockDim.x + threadIdx.x;
    if (i < NN) g_dinv[i] = rsqrtf((float)g_cnt[i] + 1.0f);  // +1 self loop
}

__device__ __forceinline__ int blockScanEx(int v, int* bsum) {
    int lane = threadIdx.x & 31, wid = threadIdx.x >> 5;
    int x = v;
#pragma unroll
    for (int d = 1; d < 32; d <<= 1) {
        int y = __shfl_up_sync(0xffffffffu, x, d);
        if (lane >= d) x += y;
    }
    __shared__ int wsum[8];
    if (lane == 31) wsum[wid] = x;
    __syncthreads();
    if (wid == 0) {
        int t = (lane < 8) ? wsum[lane] : 0;
#pragma unroll
        for (int d = 1; d < 8; d <<= 1) {
            int y = __shfl_up_sync(0xffffffffu, t, d);
            if (lane >= d) t += y;
        }
        if (lane < 8) wsum[lane] = t;
    }
    __syncthreads();
    int incl = x + (wid > 0 ? wsum[wid - 1] : 0);
    *bsum = wsum[7];
    return incl - v;
}

__global__ void k_scan1() {
    int i = blockIdx.x * 256 + threadIdx.x;
    int v = (i < NN) ? g_cnt[i] : 0;
    int bsum;
    int ex = blockScanEx(v, &bsum);
    if (i < NN) g_off[i] = ex;
    if (threadIdx.x == 0) g_bsum[blockIdx.x] = bsum;
}

__global__ void k_scan2() {
    int i = threadIdx.x;
    int v = (i < NBLK) ? g_bsum[i] : 0;
    int bsum;
    int ex = blockScanEx(v, &bsum);
    if (i < NBLK) g_boff[i] = ex;
}

__global__ void k_scan3() {
    int i = blockIdx.x * 256 + threadIdx.x;
    if (i >= NN) return;
    int o = g_off[i] + g_boff[blockIdx.x];
    g_off[i] = o;
    g_cursor[i] = o;
}

__global__ void k_fill() {
    int e = blockIdx.x * blockDim.x + threadIdx.x;
    if (e >= EE) return;
    int r = g_row[e];
    int c = g_col[e];
    int pos = atomicAdd(&g_cursor[c], 1);
    g_csr_row[pos] = r;
    g_csr_nrm[pos] = g_dinv[r] * g_dinv[c];
}

// ---------------- TF32 helpers ----------------
__device__ __forceinline__ uint32_t f2tf32(float f) {
    uint32_t u;
    asm("cvt.rna.tf32.f32 %0, %1;" : "=r"(u) : "f"(f));
    return u;
}

// ================= fused dual-B GEMM =================
// C0[M,128] = A@B0, C1[M,128] = A@B1. Block tile 128x256, 512 threads (16 warps),
// warp tile 64x32, K-chunks of 16, register prefetch of next chunk.
template <int SRCID, int DST0, int DST1>
__global__ void __launch_bounds__(512, 1) k_gemm2(
    const float* __restrict__ Aext, const float* __restrict__ B0,
    const float* __restrict__ B1, int M)
{
    const float* A = (SRCID < 0) ? Aext : (const float*)g_buf[SRCID];
    float* C0 = (float*)g_buf[DST0];
    float* C1 = (float*)g_buf[DST1];

    __shared__ uint32_t As[128][20];   // [m][k], pitch 20 (80B rows, 16B aligned)
    __shared__ uint32_t Bt[256][20];   // [n][k] (transposed, two matrices stacked)

    const int tid = threadIdx.x;
    const int lane = tid & 31;
    const int wid = tid >> 5;
    const int warpM = wid >> 3;        // 0..1
    const int warpN = wid & 7;         // 0..7
    const int rowBase = blockIdx.x * 128;

    float acc[4][4][4];
#pragma unroll
    for (int mt = 0; mt < 4; mt++)
#pragma unroll
        for (int nt = 0; nt < 4; nt++)
#pragma unroll
            for (int i = 0; i < 4; i++) acc[mt][nt][i] = 0.f;

    uint32_t aAddr[4], bAddr[4];
    {
        int ar = warpM * 64 + ((lane >> 3) & 1) * 8 + (lane & 7);
        int ac = ((lane >> 4) & 1) * 4;
#pragma unroll
        for (int mt = 0; mt < 4; mt++)
            aAddr[mt] = (uint32_t)__cvta_generic_to_shared(&As[ar + mt * 16][ac]);
        int br = warpN * 32 + (lane & 7);
        int bc = ((lane >> 3) & 1) * 4;
#pragma unroll
        for (int nt = 0; nt < 4; nt++)
            bAddr[nt] = (uint32_t)__cvta_generic_to_shared(&Bt[br + nt * 8][bc]);
    }

    // prefetch registers
    float4 pa;        // A: 512 float4/chunk, 1 per thread
    float4 pb[2];     // B: 1024 float4/chunk, 2 per thread
    const int a_row = tid >> 2;            // 0..127
    const int a_c4  = (tid & 3) * 4;       // 0,4,8,12
    const int a_grow = min(rowBase + a_row, M - 1);

#define LOADCHUNK2(KC0)                                                        \
    {                                                                          \
        pa = *(const float4*)&A[(size_t)a_grow * DD + (KC0) + a_c4];           \
        _Pragma("unroll")                                                      \
        for (int i = 0; i < 2; i++) {                                          \
            int lin = tid + i * 512;                                           \
            int mat = lin >> 9;                                                \
            int l9 = lin & 511;                                                \
            int kr = l9 >> 5;                                                  \
            int n4 = (l9 & 31) * 4;                                            \
            const float* Bs = mat ? B1 : B0;                                   \
            pb[i] = *(const float4*)&Bs[(size_t)((KC0) + kr) * DD + n4];       \
        }                                                                      \
    }

#define STORECHUNK2()                                                          \
    {                                                                          \
        *(uint4*)&As[a_row][a_c4] =                                            \
            make_uint4(f2tf32(pa.x), f2tf32(pa.y), f2tf32(pa.z), f2tf32(pa.w));\
        _Pragma("unroll")                                                      \
        for (int i = 0; i < 2; i++) {                                          \
            int lin = tid + i * 512;                                           \
            int mat = lin >> 9;                                                \
            int l9 = lin & 511;                                                \
            int kr = l9 >> 5;                                                  \
            int n = mat * 128 + (l9 & 31) * 4;                                 \
            Bt[n + 0][kr] = f2tf32(pb[i].x);                                   \
            Bt[n + 1][kr] = f2tf32(pb[i].y);                                   \
            Bt[n + 2][kr] = f2tf32(pb[i].z);                                   \
            Bt[n + 3][kr] = f2tf32(pb[i].w);                                   \
        }                                                                      \
    }

    LOADCHUNK2(0);
    STORECHUNK2();
    __syncthreads();

    for (int kc = 0; kc < 8; kc++) {
        if (kc < 7) LOADCHUNK2((kc + 1) * 16);
#pragma unroll
        for (int ks = 0; ks < 2; ks++) {
            uint32_t a[4][4], b[4][2];
#pragma unroll
            for (int nt = 0; nt < 4; nt++) {
                asm volatile("ldmatrix.sync.aligned.m8n8.x2.shared.b16 {%0,%1}, [%2];"
                             : "=r"(b[nt][0]), "=r"(b[nt][1])
                             : "r"(bAddr[nt] + ks * 32));
            }
#pragma unroll
            for (int mt = 0; mt < 4; mt++) {
                asm volatile("ldmatrix.sync.aligned.m8n8.x4.shared.b16 {%0,%1,%2,%3}, [%4];"
                             : "=r"(a[mt][0]), "=r"(a[mt][1]), "=r"(a[mt][2]), "=r"(a[mt][3])
                             : "r"(aAddr[mt] + ks * 32));
            }
#pragma unroll
            for (int mt = 0; mt < 4; mt++)
#pragma unroll
                for (int nt = 0; nt < 4; nt++) {
                    asm volatile(
                        "mma.sync.aligned.m16n8k8.row.col.f32.tf32.tf32.f32 "
                        "{%0,%1,%2,%3}, {%4,%5,%6,%7}, {%8,%9}, {%0,%1,%2,%3};"
                        : "+f"(acc[mt][nt][0]), "+f"(acc[mt][nt][1]),
                          "+f"(acc[mt][nt][2]), "+f"(acc[mt][nt][3])
                        : "r"(a[mt][0]), "r"(a[mt][1]), "r"(a[mt][2]), "r"(a[mt][3]),
                          "r"(b[nt][0]), "r"(b[nt][1]));
                }
        }
        __syncthreads();
        if (kc < 7) {
            STORECHUNK2();
            __syncthreads();
        }
    }

    const int g = lane >> 2;
    const int t = lane & 3;
#pragma unroll
    for (int mt = 0; mt < 4; mt++) {
        int r0 = rowBase + warpM * 64 + mt * 16 + g;
#pragma unroll
        for (int nt = 0; nt < 4; nt++) {
            int col = warpN * 32 + nt * 8 + t * 2;
            float* C = (col < 128) ? C0 : C1;
            int cc = col & 127;
            float2 v0 = make_float2(acc[mt][nt][0], acc[mt][nt][1]);
            float2 v1 = make_float2(acc[mt][nt][2], acc[mt][nt][3]);
            if (r0 < M)     *(float2*)&C[(size_t)r0 * DD + cc] = v0;
            if (r0 + 8 < M) *(float2*)&C[(size_t)(r0 + 8) * DD + cc] = v1;
        }
    }
#undef LOADCHUNK2
#undef STORECHUNK2
}

// ================= single-B GEMM (+bias) =================
// Block tile 128x128, 256 threads, K-chunks of 32, register prefetch.
template <int SRCID, int DSTID, bool BIAS>
__global__ void __launch_bounds__(256, 2) k_gemm(
    const float* __restrict__ Aext, const float* __restrict__ B,
    const float* __restrict__ bias, float* __restrict__ Cext, int M)
{
    const float* A = (SRCID < 0) ? Aext : (const float*)g_buf[SRCID];
    float* C = (DSTID < 0) ? Cext : (float*)g_buf[DSTID];

    __shared__ uint32_t As[128][40];
    __shared__ uint32_t Bt[128][40];

    const int tid = threadIdx.x;
    const int lane = tid & 31;
    const int wid = tid >> 5;
    const int warpM = wid >> 2;
    const int warpN = wid & 3;
    const int rowBase = blockIdx.x * 128;

    float acc[4][4][4];
#pragma unroll
    for (int mt = 0; mt < 4; mt++)
#pragma unroll
        for (int nt = 0; nt < 4; nt++)
#pragma unroll
            for (int i = 0; i < 4; i++) acc[mt][nt][i] = 0.f;

    uint32_t aAddr[4], bAddr[4];
    {
        int ar = warpM * 64 + ((lane >> 3) & 1) * 8 + (lane & 7);
        int ac = ((lane >> 4) & 1) * 4;
#pragma unroll
        for (int mt = 0; mt < 4; mt++)
            aAddr[mt] = (uint32_t)__cvta_generic_to_shared(&As[ar + mt * 16][ac]);
        int br = warpN * 32 + (lane & 7);
        int bc = ((lane >> 3) & 1) * 4;
#pragma unroll
        for (int nt = 0; nt < 4; nt++)
            bAddr[nt] = (uint32_t)__cvta_generic_to_shared(&Bt[br + nt * 8][bc]);
    }

    float4 pa[4], pb[4];
    const int a_row = tid >> 3;            // 0..31 step: lin>>3 with lin=tid+i*256
    const int a_c4  = (tid & 7) * 4;

#define LOADCHUNK1(KC0)                                                        \
    {                                                                          \
        _Pragma("unroll")                                                      \
        for (int i = 0; i < 4; i++) {                                          \
            int row = a_row + i * 32;                                          \
            int grow = min(rowBase + row, M - 1);                              \
            pa[i] = *(const float4*)&A[(size_t)grow * DD + (KC0) + a_c4];      \
        }                                                                      \
        _Pragma("unroll")                                                      \
        for (int i = 0; i < 4; i++) {                                          \
            int lin = tid + i * 256;                                           \
            int kr = lin >> 5;                                                 \
            int n4 = (lin & 31) * 4;                                           \
            pb[i] = *(const float4*)&B[(size_t)((KC0) + kr) * DD + n4];        \
        }                                                                      \
    }

#define STORECHUNK1()                                                          \
    {                                                                          \
        _Pragma("unroll")                                                      \
        for (int i = 0; i < 4; i++) {                                          \
            int row = a_row + i * 32;                                          \
            *(uint4*)&As[row][a_c4] = make_uint4(                              \
                f2tf32(pa[i].x), f2tf32(pa[i].y), f2tf32(pa[i].z), f2tf32(pa[i].w)); \
        }                                                                      \
        _Pragma("unroll")                                                      \
        for (int i = 0; i < 4; i++) {                                          \
            int lin = tid + i * 256;                                           \
            int kr = lin >> 5;                                                 \
            int n4 = (lin & 31) * 4;                                           \
            Bt[n4 + 0][kr] = f2tf32(pb[i].x);                                  \
            Bt[n4 + 1][kr] = f2tf32(pb[i].y);                                  \
            Bt[n4 + 2][kr] = f2tf32(pb[i].z);                                  \
            Bt[n4 + 3][kr] = f2tf32(pb[i].w);                                  \
        }                                                                      \
    }

    LOADCHUNK1(0);
    STORECHUNK1();
    __syncthreads();

    for (int kc = 0; kc < 4; kc++) {
        if (kc < 3) LOADCHUNK1((kc + 1) * 32);
#pragma unroll
        for (int ks = 0; ks < 4; ks++) {
            uint32_t a[4][4], b[4][2];
#pragma unroll
            for (int nt = 0; nt < 4; nt++) {
                asm volatile("ldmatrix.sync.aligned.m8n8.x2.shared.b16 {%0,%1}, [%2];"
                             : "=r"(b[nt][0]), "=r"(b[nt][1])
                             : "r"(bAddr[nt] + ks * 32));
            }
#pragma unroll
            for (int mt = 0; mt < 4; mt++) {
                asm volatile("ldmatrix.sync.aligned.m8n8.x4.shared.b16 {%0,%1,%2,%3}, [%4];"
                             : "=r"(a[mt][0]), "=r"(a[mt][1]), "=r"(a[mt][2]), "=r"(a[mt][3])
                             : "r"(aAddr[mt] + ks * 32));
            }
#pragma unroll
            for (int mt = 0; mt < 4; mt++)
#pragma unroll
                for (int nt = 0; nt < 4; nt++) {
                    asm volatile(
                        "mma.sync.aligned.m16n8k8.row.col.f32.tf32.tf32.f32 "
                        "{%0,%1,%2,%3}, {%4,%5,%6,%7}, {%8,%9}, {%0,%1,%2,%3};"
                        : "+f"(acc[mt][nt][0]), "+f"(acc[mt][nt][1]),
                          "+f"(acc[mt][nt][2]), "+f"(acc[mt][nt][3])
                        : "r"(a[mt][0]), "r"(a[mt][1]), "r"(a[mt][2]), "r"(a[mt][3]),
                          "r"(b[nt][0]), "r"(b[nt][1]));
                }
        }
        __syncthreads();
        if (kc < 3) {
            STORECHUNK1();
            __syncthreads();
        }
    }

    const int g = lane >> 2;
    const int t = lane & 3;
#pragma unroll
    for (int mt = 0; mt < 4; mt++) {
        int r0 = rowBase + warpM * 64 + mt * 16 + g;
#pragma unroll
        for (int nt = 0; nt < 4; nt++) {
            int col = warpN * 32 + nt * 8 + t * 2;
            float2 v0 = make_float2(acc[mt][nt][0], acc[mt][nt][1]);
            float2 v1 = make_float2(acc[mt][nt][2], acc[mt][nt][3]);
            if (BIAS) {
                float2 bv = *(const float2*)&bias[col];
                v0.x += bv.x; v0.y += bv.y;
                v1.x += bv.x; v1.y += bv.y;
            }
            if (r0 < M)     *(float2*)&C[(size_t)r0 * DD + col] = v0;
            if (r0 + 8 < M) *(float2*)&C[(size_t)(r0 + 8) * DD + col] = v1;
        }
    }
#undef LOADCHUNK1
#undef STORECHUNK1
}

// ---------------- CSR gather-aggregate (fused self-loop + residual + relu) ----------------
template <int RESID, int DSTID, bool RELU>
__global__ void __launch_bounds__(256) k_aggregate()
{
    int node = (blockIdx.x * blockDim.x + threadIdx.x) >> 5;
    if (node >= NN) return;
    int lane = threadIdx.x & 31;

    const float4* H4 = (const float4*)g_buf[0];
    float4 acc = make_float4(0.f, 0.f, 0.f, 0.f);

    int s = g_off[node];
    int end = s + g_cnt[node];

    int j = s;
    for (; j + 2 <= end; j += 2) {
        int r0 = g_csr_row[j];
        int r1 = g_csr_row[j + 1];
        float w0 = g_csr_nrm[j];
        float w1 = g_csr_nrm[j + 1];
        float4 h0 = H4[r0 * 32 + lane];
        float4 h1 = H4[r1 * 32 + lane];
        acc.x += h0.x * w0 + h1.x * w1;
        acc.y += h0.y * w0 + h1.y * w1;
        acc.z += h0.z * w0 + h1.z * w1;
        acc.w += h0.w * w0 + h1.w * w1;
    }
    if (j < end) {
        int r0 = g_csr_row[j];
        float w0 = g_csr_nrm[j];
        float4 h0 = H4[r0 * 32 + lane];
        acc.x += h0.x * w0;
        acc.y += h0.y * w0;
        acc.z += h0.z * w0;
        acc.w += h0.w * w0;
    }

    float d = g_dinv[node];
    float d2 = d * d;
    float4 hs = H4[node * 32 + lane];
    acc.x += hs.x * d2;
    acc.y += hs.y * d2;
    acc.z += hs.z * d2;
    acc.w += hs.w * d2;

    if (RESID >= 0) {
        float4 rv = ((const float4*)g_buf[RESID])[node * 32 + lane];
        acc.x += rv.x; acc.y += rv.y; acc.z += rv.z; acc.w += rv.w;
    }
    if (RELU) {
        acc.x = fmaxf(acc.x, 0.f);
        acc.y = fmaxf(acc.y, 0.f);
        acc.z = fmaxf(acc.z, 0.f);
        acc.w = fmaxf(acc.w, 0.f);
    }
    ((float4*)g_buf[DSTID])[node * 32 + lane] = acc;
}

extern "C" void kernel_launch(void* const* d_in, const int* in_sizes, int n_in,
                              void* d_out, int out_size)
{
    const float* x  = (const float*)d_in[0];
    const void*  ei = d_in[1];
    const float* W1 = (const float*)d_in[2];
    const float* R1 = (const float*)d_in[3];
    const float* W2 = (const float*)d_in[4];
    const float* R2 = (const float*)d_in[5];
    const float* W3 = (const float*)d_in[6];
    const float* Wh = (const float*)d_in[7];
    const float* bh = (const float*)d_in[8];
    float* out = (float*)d_out;

    const int GEMM_GRID = (NN + 127) / 128;
    const int AGG_GRID  = (NN * 32 + 255) / 256;
    const int E_GRID    = (EE + 255) / 256;
    const int N_GRID    = (NN + 255) / 256;

    // ---- CSR prep ----
    k_detect<<<1, 32>>>(ei);
    k_cnt_init<<<N_GRID, 256>>>();
    k_count<<<E_GRID, 256>>>(ei);
    k_dinv<<<N_GRID, 256>>>();
    k_scan1<<<NBLK, 256>>>();
    k_scan2<<<1, 256>>>();
    k_scan3<<<NBLK, 256>>>();
    k_fill<<<E_GRID, 256>>>();

    // ---- layer 1: x -> buf2 (residual + relu) ----
    k_gemm2<-1, 0, 1><<<GEMM_GRID, 512>>>(x, W1, R1, NN);   // H = x@W1, res = x@R1
    k_aggregate<1, 2, true><<<AGG_GRID, 256>>>();           // X = relu(agg + res)

    // ---- layer 2: buf2 -> buf2 (residual + relu) ----
    k_gemm2<2, 0, 1><<<GEMM_GRID, 512>>>(nullptr, W2, R2, NN); // H = X@W2, res = X@R2
    k_aggregate<1, 2, true><<<AGG_GRID, 256>>>();              // X = relu(agg + res)

    // ---- layer 3: buf2 -> buf1 (no residual, no act) ----
    k_gemm<2, 0, false><<<GEMM_GRID, 256>>>(nullptr, W3, nullptr, nullptr, NN); // H = X@W3
    k_aggregate<-1, 1, false><<<AGG_GRID, 256>>>();                             // buf1 = agg

    // ---- head: out = buf1 @ Wh + bh ----
    k_gemm<1, -1, true><<<GEMM_GRID, 256>>>(nullptr, Wh, bh, out, NN);
}

// round 11
// speedup vs baseline: 2.6467x; 1.0807x over previous
#include <cuda_runtime.h>
#include <cuda_fp16.h>
#include <cstdint>

#define NN 50000
#define DD 128
#define EE 600000
#define NBLK 196   // ceil(NN/256)

// ---- scratch: sanctioned __device__ globals, statically addressed only ----
// g_Hh = H (x@W) in fp16 (gather-only buffer); g_buf[0] = residual, g_buf[1] = X
__device__ __align__(256) __half g_Hh[NN * DD];
__device__ __align__(256) float  g_buf[2][NN * DD];
__device__ float g_dinv[NN];
__device__ int   g_row[EE];
__device__ int   g_col[EE];
__device__ int   g_cnt[NN];
__device__ int   g_off[NN];
__device__ int   g_cursor[NN];
__device__ int   g_bsum[NBLK];
__device__ int   g_boff[NBLK];
__device__ int   g_csr_row[EE];
__device__ float g_csr_nrm[EE];
__device__ int   g_is64;

// ---------------- edge index dtype detection ----------------
__global__ void k_detect(const void* __restrict__ ei) {
    if (threadIdx.x != 0 || blockIdx.x != 0) return;
    const long long* p = (const long long*)ei;
    int ok = 1;
    for (int i = 0; i < 64; i++) {
        long long v = p[i];
        if (v < 0 || v >= NN) { ok = 0; break; }
    }
    g_is64 = ok;
}

// ---------------- CSR construction ----------------
__global__ void k_cnt_init() {
    int i = blockIdx.x * blockDim.x + threadIdx.x;
    if (i < NN) g_cnt[i] = 0;
}

__global__ void k_count(const void* __restrict__ ei) {
    int e = blockIdx.x * blockDim.x + threadIdx.x;
    if (e >= EE) return;
    int r, c;
    if (g_is64) {
        const long long* p = (const long long*)ei;
        r = (int)p[e];
        c = (int)p[EE + e];
    } else {
        const int* p = (const int*)ei;
        r = p[e];
        c = p[EE + e];
    }
    r = min(max(r, 0), NN - 1);
    c = min(max(c, 0), NN - 1);
    g_row[e] = r;
    g_col[e] = c;
    atomicAdd(&g_cnt[c], 1);
}

__global__ void k_dinv() {
    int i = blockIdx.x * blockDim.x + threadIdx.x;
    if (i < NN) g_dinv[i] = rsqrtf((float)g_cnt[i] + 1.0f);  // +1 self loop
}

__device__ __forceinline__ int blockScanEx(int v, int* bsum) {
    int lane = threadIdx.x & 31, wid = threadIdx.x >> 5;
    int x = v;
#pragma unroll
    for (int d = 1; d < 32; d <<= 1) {
        int y = __shfl_up_sync(0xffffffffu, x, d);
        if (lane >= d) x += y;
    }
    __shared__ int wsum[8];
    if (lane == 31) wsum[wid] = x;
    __syncthreads();
    if (wid == 0) {
        int t = (lane < 8) ? wsum[lane] : 0;
#pragma unroll
        for (int d = 1; d < 8; d <<= 1) {
            int y = __shfl_up_sync(0xffffffffu, t, d);
            if (lane >= d) t += y;
        }
        if (lane < 8) wsum[lane] = t;
    }
    __syncthreads();
    int incl = x + (wid > 0 ? wsum[wid - 1] : 0);
    *bsum = wsum[7];
    return incl - v;
}

__global__ void k_scan1() {
    int i = blockIdx.x * 256 + threadIdx.x;
    int v = (i < NN) ? g_cnt[i] : 0;
    int bsum;
    int ex = blockScanEx(v, &bsum);
    if (i < NN) g_off[i] = ex;
    if (threadIdx.x == 0) g_bsum[blockIdx.x] = bsum;
}

__global__ void k_scan2() {
    int i = threadIdx.x;
    int v = (i < NBLK) ? g_bsum[i] : 0;
    int bsum;
    int ex = blockScanEx(v, &bsum);
    if (i < NBLK) g_boff[i] = ex;
}

__global__ void k_scan3() {
    int i = blockIdx.x * 256 + threadIdx.x;
    if (i >= NN) return;
    int o = g_off[i] + g_boff[blockIdx.x];
    g_off[i] = o;
    g_cursor[i] = o;
}

__global__ void k_fill() {
    int e = blockIdx.x * blockDim.x + threadIdx.x;
    if (e >= EE) return;
    int r = g_row[e];
    int c = g_col[e];
    int pos = atomicAdd(&g_cursor[c], 1);
    g_csr_row[pos] = r;
    g_csr_nrm[pos] = g_dinv[r] * g_dinv[c];
}

// ---------------- TF32 helpers ----------------
__device__ __forceinline__ uint32_t f2tf32(float f) {
    uint32_t u;
    asm("cvt.rna.tf32.f32 %0, %1;" : "=r"(u) : "f"(f));
    return u;
}

// ================= fused dual-B GEMM =================
// g_Hh[M,128](fp16) = A@B0, g_buf[DST1][M,128](fp32) = A@B1.
// Block tile 128x256, 512 threads (16 warps), warp tile 64x32, K-chunks of 16, reg prefetch.
template <int SRCID, int DST1>
__global__ void __launch_bounds__(512, 1) k_gemm2(
    const float* __restrict__ Aext, const float* __restrict__ B0,
    const float* __restrict__ B1, int M)
{
    const float* A = (SRCID < 0) ? Aext : (const float*)g_buf[SRCID];
    float* C1 = (float*)g_buf[DST1];

    __shared__ uint32_t As[128][20];
    __shared__ uint32_t Bt[256][20];

    const int tid = threadIdx.x;
    const int lane = tid & 31;
    const int wid = tid >> 5;
    const int warpM = wid >> 3;
    const int warpN = wid & 7;
    const int rowBase = blockIdx.x * 128;

    float acc[4][4][4];
#pragma unroll
    for (int mt = 0; mt < 4; mt++)
#pragma unroll
        for (int nt = 0; nt < 4; nt++)
#pragma unroll
            for (int i = 0; i < 4; i++) acc[mt][nt][i] = 0.f;

    uint32_t aAddr[4], bAddr[4];
    {
        int ar = warpM * 64 + ((lane >> 3) & 1) * 8 + (lane & 7);
        int ac = ((lane >> 4) & 1) * 4;
#pragma unroll
        for (int mt = 0; mt < 4; mt++)
            aAddr[mt] = (uint32_t)__cvta_generic_to_shared(&As[ar + mt * 16][ac]);
        int br = warpN * 32 + (lane & 7);
        int bc = ((lane >> 3) & 1) * 4;
#pragma unroll
        for (int nt = 0; nt < 4; nt++)
            bAddr[nt] = (uint32_t)__cvta_generic_to_shared(&Bt[br + nt * 8][bc]);
    }

    float4 pa;
    float4 pb[2];
    const int a_row = tid >> 2;
    const int a_c4  = (tid & 3) * 4;
    const int a_grow = min(rowBase + a_row, M - 1);

#define LOADCHUNK2(KC0)                                                        \
    {                                                                          \
        pa = *(const float4*)&A[(size_t)a_grow * DD + (KC0) + a_c4];           \
        _Pragma("unroll")                                                      \
        for (int i = 0; i < 2; i++) {                                          \
            int lin = tid + i * 512;                                           \
            int mat = lin >> 9;                                                \
            int l9 = lin & 511;                                                \
            int kr = l9 >> 5;                                                  \
            int n4 = (l9 & 31) * 4;                                            \
            const float* Bs = mat ? B1 : B0;                                   \
            pb[i] = *(const float4*)&Bs[(size_t)((KC0) + kr) * DD + n4];       \
        }                                                                      \
    }

#define STORECHUNK2()                                                          \
    {                                                                          \
        *(uint4*)&As[a_row][a_c4] =                                            \
            make_uint4(f2tf32(pa.x), f2tf32(pa.y), f2tf32(pa.z), f2tf32(pa.w));\
        _Pragma("unroll")                                                      \
        for (int i = 0; i < 2; i++) {                                          \
            int lin = tid + i * 512;                                           \
            int mat = lin >> 9;                                                \
            int l9 = lin & 511;                                                \
            int kr = l9 >> 5;                                                  \
            int n = mat * 128 + (l9 & 31) * 4;                                 \
            Bt[n + 0][kr] = f2tf32(pb[i].x);                                   \
            Bt[n + 1][kr] = f2tf32(pb[i].y);                                   \
            Bt[n + 2][kr] = f2tf32(pb[i].z);                                   \
            Bt[n + 3][kr] = f2tf32(pb[i].w);                                   \
        }                                                                      \
    }

    LOADCHUNK2(0);
    STORECHUNK2();
    __syncthreads();

    for (int kc = 0; kc < 8; kc++) {
        if (kc < 7) LOADCHUNK2((kc + 1) * 16);
#pragma unroll
        for (int ks = 0; ks < 2; ks++) {
            uint32_t a[4][4], b[4][2];
#pragma unroll
            for (int nt = 0; nt < 4; nt++) {
                asm volatile("ldmatrix.sync.aligned.m8n8.x2.shared.b16 {%0,%1}, [%2];"
                             : "=r"(b[nt][0]), "=r"(b[nt][1])
                             : "r"(bAddr[nt] + ks * 32));
            }
#pragma unroll
            for (int mt = 0; mt < 4; mt++) {
                asm volatile("ldmatrix.sync.aligned.m8n8.x4.shared.b16 {%0,%1,%2,%3}, [%4];"
                             : "=r"(a[mt][0]), "=r"(a[mt][1]), "=r"(a[mt][2]), "=r"(a[mt][3])
                             : "r"(aAddr[mt] + ks * 32));
            }
#pragma unroll
            for (int mt = 0; mt < 4; mt++)
#pragma unroll
                for (int nt = 0; nt < 4; nt++) {
                    asm volatile(
                        "mma.sync.aligned.m16n8k8.row.col.f32.tf32.tf32.f32 "
                        "{%0,%1,%2,%3}, {%4,%5,%6,%7}, {%8,%9}, {%0,%1,%2,%3};"
                        : "+f"(acc[mt][nt][0]), "+f"(acc[mt][nt][1]),
                          "+f"(acc[mt][nt][2]), "+f"(acc[mt][nt][3])
                        : "r"(a[mt][0]), "r"(a[mt][1]), "r"(a[mt][2]), "r"(a[mt][3]),
                          "r"(b[nt][0]), "r"(b[nt][1]));
                }
        }
        __syncthreads();
        if (kc < 7) {
            STORECHUNK2();
            __syncthreads();
        }
    }

    const int g = lane >> 2;
    const int t = lane & 3;
#pragma unroll
    for (int mt = 0; mt < 4; mt++) {
        int r0 = rowBase + warpM * 64 + mt * 16 + g;
#pragma unroll
        for (int nt = 0; nt < 4; nt++) {
            int col = warpN * 32 + nt * 8 + t * 2;
            float2 v0 = make_float2(acc[mt][nt][0], acc[mt][nt][1]);
            float2 v1 = make_float2(acc[mt][nt][2], acc[mt][nt][3]);
            if (col < 128) {
                // H output -> fp16
                if (r0 < M)     *(__half2*)&g_Hh[(size_t)r0 * DD + col] = __floats2half2_rn(v0.x, v0.y);
                if (r0 + 8 < M) *(__half2*)&g_Hh[(size_t)(r0 + 8) * DD + col] = __floats2half2_rn(v1.x, v1.y);
            } else {
                int cc = col - 128;
                if (r0 < M)     *(float2*)&C1[(size_t)r0 * DD + cc] = v0;
                if (r0 + 8 < M) *(float2*)&C1[(size_t)(r0 + 8) * DD + cc] = v1;
            }
        }
    }
#undef LOADCHUNK2
#undef STORECHUNK2
}

// ================= single-B GEMM =================
// Block tile 128x128, 256 threads, K-chunks of 32, reg prefetch.
// HALFOUT: write g_Hh (fp16); else write Cext (fp32, +bias optional).
template <int SRCID, bool HALFOUT, bool BIAS>
__global__ void __launch_bounds__(256, 2) k_gemm(
    const float* __restrict__ Aext, const float* __restrict__ B,
    const float* __restrict__ bias, float* __restrict__ Cext, int M)
{
    const float* A = (SRCID < 0) ? Aext : (const float*)g_buf[SRCID];

    __shared__ uint32_t As[128][40];
    __shared__ uint32_t Bt[128][40];

    const int tid = threadIdx.x;
    const int lane = tid & 31;
    const int wid = tid >> 5;
    const int warpM = wid >> 2;
    const int warpN = wid & 3;
    const int rowBase = blockIdx.x * 128;

    float acc[4][4][4];
#pragma unroll
    for (int mt = 0; mt < 4; mt++)
#pragma unroll
        for (int nt = 0; nt < 4; nt++)
#pragma unroll
            for (int i = 0; i < 4; i++) acc[mt][nt][i] = 0.f;

    uint32_t aAddr[4], bAddr[4];
    {
        int ar = warpM * 64 + ((lane >> 3) & 1) * 8 + (lane & 7);
        int ac = ((lane >> 4) & 1) * 4;
#pragma unroll
        for (int mt = 0; mt < 4; mt++)
            aAddr[mt] = (uint32_t)__cvta_generic_to_shared(&As[ar + mt * 16][ac]);
        int br = warpN * 32 + (lane & 7);
        int bc = ((lane >> 3) & 1) * 4;
#pragma unroll
        for (int nt = 0; nt < 4; nt++)
            bAddr[nt] = (uint32_t)__cvta_generic_to_shared(&Bt[br + nt * 8][bc]);
    }

    float4 pa[4], pb[4];
    const int a_row = tid >> 3;
    const int a_c4  = (tid & 7) * 4;

#define LOADCHUNK1(KC0)                                                        \
    {                                                                          \
        _Pragma("unroll")                                                      \
        for (int i = 0; i < 4; i++) {                                          \
            int row = a_row + i * 32;                                          \
            int grow = min(rowBase + row, M - 1);                              \
            pa[i] = *(const float4*)&A[(size_t)grow * DD + (KC0) + a_c4];      \
        }                                                                      \
        _Pragma("unroll")                                                      \
        for (int i = 0; i < 4; i++) {                                          \
            int lin = tid + i * 256;                                           \
            int kr = lin >> 5;                                                 \
            int n4 = (lin & 31) * 4;                                           \
            pb[i] = *(const float4*)&B[(size_t)((KC0) + kr) * DD + n4];        \
        }                                                                      \
    }

#define STORECHUNK1()                                                          \
    {                                                                          \
        _Pragma("unroll")                                                      \
        for (int i = 0; i < 4; i++) {                                          \
            int row = a_row + i * 32;                                          \
            *(uint4*)&As[row][a_c4] = make_uint4(                              \
                f2tf32(pa[i].x), f2tf32(pa[i].y), f2tf32(pa[i].z), f2tf32(pa[i].w)); \
        }                                                                      \
        _Pragma("unroll")                                                      \
        for (int i = 0; i < 4; i++) {                                          \
            int lin = tid + i * 256;                                           \
            int kr = lin >> 5;                                                 \
            int n4 = (lin & 31) * 4;                                           \
            Bt[n4 + 0][kr] = f2tf32(pb[i].x);                                  \
            Bt[n4 + 1][kr] = f2tf32(pb[i].y);                                  \
            Bt[n4 + 2][kr] = f2tf32(pb[i].z);                                  \
            Bt[n4 + 3][kr] = f2tf32(pb[i].w);                                  \
        }                                                                      \
    }

    LOADCHUNK1(0);
    STORECHUNK1();
    __syncthreads();

    for (int kc = 0; kc < 4; kc++) {
        if (kc < 3) LOADCHUNK1((kc + 1) * 32);
#pragma unroll
        for (int ks = 0; ks < 4; ks++) {
            uint32_t a[4][4], b[4][2];
#pragma unroll
            for (int nt = 0; nt < 4; nt++) {
                asm volatile("ldmatrix.sync.aligned.m8n8.x2.shared.b16 {%0,%1}, [%2];"
                             : "=r"(b[nt][0]), "=r"(b[nt][1])
                             : "r"(bAddr[nt] + ks * 32));
            }
#pragma unroll
            for (int mt = 0; mt < 4; mt++) {
                asm volatile("ldmatrix.sync.aligned.m8n8.x4.shared.b16 {%0,%1,%2,%3}, [%4];"
                             : "=r"(a[mt][0]), "=r"(a[mt][1]), "=r"(a[mt][2]), "=r"(a[mt][3])
                             : "r"(aAddr[mt] + ks * 32));
            }
#pragma unroll
            for (int mt = 0; mt < 4; mt++)
#pragma unroll
                for (int nt = 0; nt < 4; nt++) {
                    asm volatile(
                        "mma.sync.aligned.m16n8k8.row.col.f32.tf32.tf32.f32 "
                        "{%0,%1,%2,%3}, {%4,%5,%6,%7}, {%8,%9}, {%0,%1,%2,%3};"
                        : "+f"(acc[mt][nt][0]), "+f"(acc[mt][nt][1]),
                          "+f"(acc[mt][nt][2]), "+f"(acc[mt][nt][3])
                        : "r"(a[mt][0]), "r"(a[mt][1]), "r"(a[mt][2]), "r"(a[mt][3]),
                          "r"(b[nt][0]), "r"(b[nt][1]));
                }
        }
        __syncthreads();
        if (kc < 3) {
            STORECHUNK1();
            __syncthreads();
        }
    }

    const int g = lane >> 2;
    const int t = lane & 3;
#pragma unroll
    for (int mt = 0; mt < 4; mt++) {
        int r0 = rowBase + warpM * 64 + mt * 16 + g;
#pragma unroll
        for (int nt = 0; nt < 4; nt++) {
            int col = warpN * 32 + nt * 8 + t * 2;
            float2 v0 = make_float2(acc[mt][nt][0], acc[mt][nt][1]);
            float2 v1 = make_float2(acc[mt][nt][2], acc[mt][nt][3]);
            if (HALFOUT) {
                if (r0 < M)     *(__half2*)&g_Hh[(size_t)r0 * DD + col] = __floats2half2_rn(v0.x, v0.y);
                if (r0 + 8 < M) *(__half2*)&g_Hh[(size_t)(r0 + 8) * DD + col] = __floats2half2_rn(v1.x, v1.y);
            } else {
                if (BIAS) {
                    float2 bv = *(const float2*)&bias[col];
                    v0.x += bv.x; v0.y += bv.y;
                    v1.x += bv.x; v1.y += bv.y;
                }
                if (r0 < M)     *(float2*)&Cext[(size_t)r0 * DD + col] = v0;
                if (r0 + 8 < M) *(float2*)&Cext[(size_t)(r0 + 8) * DD + col] = v1;
            }
        }
    }
#undef LOADCHUNK1
#undef STORECHUNK1
}

// ---------------- CSR gather-aggregate (fp16 H, fused self-loop + residual + relu) ----------------
// One warp per node; lane covers 4 columns (uint2 = 4 halves). fp32 accumulate.
template <int RESID, int DSTID, bool RELU>
__global__ void __launch_bounds__(256) k_aggregate()
{
    int node = (blockIdx.x * blockDim.x + threadIdx.x) >> 5;
    if (node >= NN) return;
    int lane = threadIdx.x & 31;

    float4 acc = make_float4(0.f, 0.f, 0.f, 0.f);

    int s = g_off[node];
    int end = s + g_cnt[node];

#define GATHER(R, W)                                                           \
    {                                                                          \
        uint2 u = *(const uint2*)&g_Hh[(size_t)(R) * DD + lane * 4];           \
        float2 f01 = __half22float2(*(__half2*)&u.x);                          \
        float2 f23 = __half22float2(*(__half2*)&u.y);                          \
        acc.x += f01.x * (W);                                                  \
        acc.y += f01.y * (W);                                                  \
        acc.z += f23.x * (W);                                                  \
        acc.w += f23.y * (W);                                                  \
    }

    int j = s;
    for (; j + 2 <= end; j += 2) {
        int r0 = g_csr_row[j];
        int r1 = g_csr_row[j + 1];
        float w0 = g_csr_nrm[j];
        float w1 = g_csr_nrm[j + 1];
        GATHER(r0, w0);
        GATHER(r1, w1);
    }
    if (j < end) {
        int r0 = g_csr_row[j];
        float w0 = g_csr_nrm[j];
        GATHER(r0, w0);
    }

    // self loop
    float d = g_dinv[node];
    GATHER(node, d * d);
#undef GATHER

    if (RESID >= 0) {
        float4 rv = ((const float4*)g_buf[RESID < 0 ? 0 : RESID])[node * 32 + lane];
        acc.x += rv.x; acc.y += rv.y; acc.z += rv.z; acc.w += rv.w;
    }
    if (RELU) {
        acc.x = fmaxf(acc.x, 0.f);
        acc.y = fmaxf(acc.y, 0.f);
        acc.z = fmaxf(acc.z, 0.f);
        acc.w = fmaxf(acc.w, 0.f);
    }
    ((float4*)g_buf[DSTID])[node * 32 + lane] = acc;
}

extern "C" void kernel_launch(void* const* d_in, const int* in_sizes, int n_in,
                              void* d_out, int out_size)
{
    const float* x  = (const float*)d_in[0];
    const void*  ei = d_in[1];
    const float* W1 = (const float*)d_in[2];
    const float* R1 = (const float*)d_in[3];
    const float* W2 = (const float*)d_in[4];
    const float* R2 = (const float*)d_in[5];
    const float* W3 = (const float*)d_in[6];
    const float* Wh = (const float*)d_in[7];
    const float* bh = (const float*)d_in[8];
    float* out = (float*)d_out;

    const int GEMM_GRID = (NN + 127) / 128;
    const int AGG_GRID  = (NN * 32 + 255) / 256;
    const int E_GRID    = (EE + 255) / 256;
    const int N_GRID    = (NN + 255) / 256;

    // ---- CSR prep ----
    k_detect<<<1, 32>>>(ei);
    k_cnt_init<<<N_GRID, 256>>>();
    k_count<<<E_GRID, 256>>>(ei);
    k_dinv<<<N_GRID, 256>>>();
    k_scan1<<<NBLK, 256>>>();
    k_scan2<<<1, 256>>>();
    k_scan3<<<NBLK, 256>>>();
    k_fill<<<E_GRID, 256>>>();

    // ---- layer 1: x -> buf1=X (residual + relu) ----
    k_gemm2<-1, 0><<<GEMM_GRID, 512>>>(x, W1, R1, NN);   // Hh = half(x@W1), buf0 = x@R1
    k_aggregate<0, 1, true><<<AGG_GRID, 256>>>();        // X = relu(agg + buf0)

    // ---- layer 2: X -> X (residual + relu) ----
    k_gemm2<1, 0><<<GEMM_GRID, 512>>>(nullptr, W2, R2, NN); // Hh = half(X@W2), buf0 = X@R2
    k_aggregate<0, 1, true><<<AGG_GRID, 256>>>();           // X = relu(agg + buf0)

    // ---- layer 3: X -> buf0 (no residual, no act) ----
    k_gemm<1, true, false><<<GEMM_GRID, 256>>>(nullptr, W3, nullptr, nullptr, NN); // Hh = half(X@W3)
    k_aggregate<-1, 0, false><<<AGG_GRID, 256>>>();                                // buf0 = agg

    // ---- head: out = buf0 @ Wh + bh ----
    k_gemm<0, false, true><<<GEMM_GRID, 256>>>(nullptr, Wh, bh, out, NN);
}

// round 15
// speedup vs baseline: 2.6824x; 1.0135x over previous
#include <cuda_runtime.h>
#include <cuda_fp16.h>
#include <cstdint>

#define NN 50000
#define DD 128
#define EE 600000
#define NBLK 196   // ceil(NN/256)

// ---- scratch ----
__device__ __align__(256) __half g_Hh[NN * DD];
__device__ __align__(256) float  g_buf[2][NN * DD];
__device__ float g_dinv[NN];
__device__ int   g_row[EE];
__device__ int   g_col[EE];
__device__ int   g_cnt[NN];
__device__ int   g_off[NN];
__device__ int   g_cursor[NN];
__device__ int   g_bsum[NBLK];
__device__ int   g_boff[NBLK];
__device__ int   g_csr_row[EE];
__device__ float g_csr_nrm[EE];
__device__ int   g_is64;

// ---------------- init: zero counts + dtype detect (thread (0,0)) ----------------
__global__ void k_init(const void* __restrict__ ei) {
    int i = blockIdx.x * blockDim.x + threadIdx.x;
    if (i < NN) g_cnt[i] = 0;
    if (i == 0) {
        const long long* p = (const long long*)ei;
        int ok = 1;
        for (int t = 0; t < 64; t++) {
            long long v = p[t];
            if (v < 0 || v >= NN) { ok = 0; break; }
        }
        g_is64 = ok;
    }
}

__global__ void k_count(const void* __restrict__ ei) {
    int e = blockIdx.x * blockDim.x + threadIdx.x;
    if (e >= EE) return;
    int r, c;
    if (g_is64) {
        const long long* p = (const long long*)ei;
        r = (int)p[e];
        c = (int)p[EE + e];
    } else {
        const int* p = (const int*)ei;
        r = p[e];
        c = p[EE + e];
    }
    r = min(max(r, 0), NN - 1);
    c = min(max(c, 0), NN - 1);
    g_row[e] = r;
    g_col[e] = c;
    atomicAdd(&g_cnt[c], 1);
}

__device__ __forceinline__ int blockScanEx(int v, int* bsum) {
    int lane = threadIdx.x & 31, wid = threadIdx.x >> 5;
    int x = v;
#pragma unroll
    for (int d = 1; d < 32; d <<= 1) {
        int y = __shfl_up_sync(0xffffffffu, x, d);
        if (lane >= d) x += y;
    }
    __shared__ int wsum[8];
    if (lane == 31) wsum[wid] = x;
    __syncthreads();
    if (wid == 0) {
        int t = (lane < 8) ? wsum[lane] : 0;
#pragma unroll
        for (int d = 1; d < 8; d <<= 1) {
            int y = __shfl_up_sync(0xffffffffu, t, d);
            if (lane >= d) t += y;
        }
        if (lane < 8) wsum[lane] = t;
    }
    __syncthreads();
    int incl = x + (wid > 0 ? wsum[wid - 1] : 0);
    *bsum = wsum[7];
    return incl - v;
}

// scan pass 1 + dinv (fused)
__global__ void k_scan1() {
    int i = blockIdx.x * 256 + threadIdx.x;
    int v = (i < NN) ? g_cnt[i] : 0;
    int bsum;
    int ex = blockScanEx(v, &bsum);
    if (i < NN) {
        g_off[i] = ex;
        g_dinv[i] = rsqrtf((float)v + 1.0f);   // +1 self loop
    }
    if (threadIdx.x == 0) g_bsum[blockIdx.x] = bsum;
}

__global__ void k_scan2() {
    int i = threadIdx.x;
    int v = (i < NBLK) ? g_bsum[i] : 0;
    int bsum;
    int ex = blockScanEx(v, &bsum);
    if (i < NBLK) g_boff[i] = ex;
}

__global__ void k_scan3() {
    int i = blockIdx.x * 256 + threadIdx.x;
    if (i >= NN) return;
    int o = g_off[i] + g_boff[blockIdx.x];
    g_off[i] = o;
    g_cursor[i] = o;
}

__global__ void k_fill() {
    int e = blockIdx.x * blockDim.x + threadIdx.x;
    if (e >= EE) return;
    int r = g_row[e];
    int c = g_col[e];
    int pos = atomicAdd(&g_cursor[c], 1);
    g_csr_row[pos] = r;
    g_csr_nrm[pos] = g_dinv[r] * g_dinv[c];
}

// ---------------- TF32 helpers ----------------
__device__ __forceinline__ uint32_t f2tf32(float f) {
    uint32_t u;
    asm("cvt.rna.tf32.f32 %0, %1;" : "=r"(u) : "f"(f));
    return u;
}

// ================= fused dual-B GEMM =================
// g_Hh[M,128](fp16) = A@B0, g_buf[DST1][M,128](fp32) = A@B1.
template <int SRCID, int DST1>
__global__ void __launch_bounds__(512, 1) k_gemm2(
    const float* __restrict__ Aext, const float* __restrict__ B0,
    const float* __restrict__ B1, int M)
{
    const float* A = (SRCID < 0) ? Aext : (const float*)g_buf[SRCID];
    float* C1 = (float*)g_buf[DST1];

    __shared__ uint32_t As[128][20];
    __shared__ uint32_t Bt[256][20];

    const int tid = threadIdx.x;
    const int lane = tid & 31;
    const int wid = tid >> 5;
    const int warpM = wid >> 3;
    const int warpN = wid & 7;
    const int rowBase = blockIdx.x * 128;

    float acc[4][4][4];
#pragma unroll
    for (int mt = 0; mt < 4; mt++)
#pragma unroll
        for (int nt = 0; nt < 4; nt++)
#pragma unroll
            for (int i = 0; i < 4; i++) acc[mt][nt][i] = 0.f;

    uint32_t aAddr[4], bAddr[4];
    {
        int ar = warpM * 64 + ((lane >> 3) & 1) * 8 + (lane & 7);
        int ac = ((lane >> 4) & 1) * 4;
#pragma unroll
        for (int mt = 0; mt < 4; mt++)
            aAddr[mt] = (uint32_t)__cvta_generic_to_shared(&As[ar + mt * 16][ac]);
        int br = warpN * 32 + (lane & 7);
        int bc = ((lane >> 3) & 1) * 4;
#pragma unroll
        for (int nt = 0; nt < 4; nt++)
            bAddr[nt] = (uint32_t)__cvta_generic_to_shared(&Bt[br + nt * 8][bc]);
    }

    float4 pa;
    float4 pb[2];
    const int a_row = tid >> 2;
    const int a_c4  = (tid & 3) * 4;
    const int a_grow = min(rowBase + a_row, M - 1);

#define LOADCHUNK2(KC0)                                                        \
    {                                                                          \
        pa = *(const float4*)&A[(size_t)a_grow * DD + (KC0) + a_c4];           \
        _Pragma("unroll")                                                      \
        for (int i = 0; i < 2; i++) {                                          \
            int lin = tid + i * 512;                                           \
            int mat = lin >> 9;                                                \
            int l9 = lin & 511;                                                \
            int kr = l9 >> 5;                                                  \
            int n4 = (l9 & 31) * 4;                                            \
            const float* Bs = mat ? B1 : B0;                                   \
            pb[i] = *(const float4*)&Bs[(size_t)((KC0) + kr) * DD + n4];       \
        }                                                                      \
    }

#define STORECHUNK2()                                                          \
    {                                                                          \
        *(uint4*)&As[a_row][a_c4] =                                            \
            make_uint4(f2tf32(pa.x), f2tf32(pa.y), f2tf32(pa.z), f2tf32(pa.w));\
        _Pragma("unroll")                                                      \
        for (int i = 0; i < 2; i++) {                                          \
            int lin = tid + i * 512;                                           \
            int mat = lin >> 9;                                                \
            int l9 = lin & 511;                                                \
            int kr = l9 >> 5;                                                  \
            int n = mat * 128 + (l9 & 31) * 4;                                 \
            Bt[n + 0][kr] = f2tf32(pb[i].x);                                   \
            Bt[n + 1][kr] = f2tf32(pb[i].y);                                   \
            Bt[n + 2][kr] = f2tf32(pb[i].z);                                   \
            Bt[n + 3][kr] = f2tf32(pb[i].w);                                   \
        }                                                                      \
    }

    LOADCHUNK2(0);
    STORECHUNK2();
    __syncthreads();

    for (int kc = 0; kc < 8; kc++) {
        if (kc < 7) LOADCHUNK2((kc + 1) * 16);
#pragma unroll
        for (int ks = 0; ks < 2; ks++) {
            uint32_t a[4][4], b[4][2];
#pragma unroll
            for (int nt = 0; nt < 4; nt++) {
                asm volatile("ldmatrix.sync.aligned.m8n8.x2.shared.b16 {%0,%1}, [%2];"
                             : "=r"(b[nt][0]), "=r"(b[nt][1])
                             : "r"(bAddr[nt] + ks * 32));
            }
#pragma unroll
            for (int mt = 0; mt < 4; mt++) {
                asm volatile("ldmatrix.sync.aligned.m8n8.x4.shared.b16 {%0,%1,%2,%3}, [%4];"
                             : "=r"(a[mt][0]), "=r"(a[mt][1]), "=r"(a[mt][2]), "=r"(a[mt][3])
                             : "r"(aAddr[mt] + ks * 32));
            }
#pragma unroll
            for (int mt = 0; mt < 4; mt++)
#pragma unroll
                for (int nt = 0; nt < 4; nt++) {
                    asm volatile(
                        "mma.sync.aligned.m16n8k8.row.col.f32.tf32.tf32.f32 "
                        "{%0,%1,%2,%3}, {%4,%5,%6,%7}, {%8,%9}, {%0,%1,%2,%3};"
                        : "+f"(acc[mt][nt][0]), "+f"(acc[mt][nt][1]),
                          "+f"(acc[mt][nt][2]), "+f"(acc[mt][nt][3])
                        : "r"(a[mt][0]), "r"(a[mt][1]), "r"(a[mt][2]), "r"(a[mt][3]),
                          "r"(b[nt][0]), "r"(b[nt][1]));
                }
        }
        __syncthreads();
        if (kc < 7) {
            STORECHUNK2();
            __syncthreads();
        }
    }

    const int g = lane >> 2;
    const int t = lane & 3;
#pragma unroll
    for (int mt = 0; mt < 4; mt++) {
        int r0 = rowBase + warpM * 64 + mt * 16 + g;
#pragma unroll
        for (int nt = 0; nt < 4; nt++) {
            int col = warpN * 32 + nt * 8 + t * 2;
            float2 v0 = make_float2(acc[mt][nt][0], acc[mt][nt][1]);
            float2 v1 = make_float2(acc[mt][nt][2], acc[mt][nt][3]);
            if (col < 128) {
                if (r0 < M)     *(__half2*)&g_Hh[(size_t)r0 * DD + col] = __floats2half2_rn(v0.x, v0.y);
                if (r0 + 8 < M) *(__half2*)&g_Hh[(size_t)(r0 + 8) * DD + col] = __floats2half2_rn(v1.x, v1.y);
            } else {
                int cc = col - 128;
                if (r0 < M)     *(float2*)&C1[(size_t)r0 * DD + cc] = v0;
                if (r0 + 8 < M) *(float2*)&C1[(size_t)(r0 + 8) * DD + cc] = v1;
            }
        }
    }
#undef LOADCHUNK2
#undef STORECHUNK2
}

// ================= single-B GEMM =================
template <int SRCID, bool HALFOUT, bool BIAS>
__global__ void __launch_bounds__(256, 2) k_gemm(
    const float* __restrict__ Aext, const float* __restrict__ B,
    const float* __restrict__ bias, float* __restrict__ Cext, int M)
{
    const float* A = (SRCID < 0) ? Aext : (const float*)g_buf[SRCID];

    __shared__ uint32_t As[128][40];
    __shared__ uint32_t Bt[128][40];

    const int tid = threadIdx.x;
    const int lane = tid & 31;
    const int wid = tid >> 5;
    const int warpM = wid >> 2;
    const int warpN = wid & 3;
    const int rowBase = blockIdx.x * 128;

    float acc[4][4][4];
#pragma unroll
    for (int mt = 0; mt < 4; mt++)
#pragma unroll
        for (int nt = 0; nt < 4; nt++)
#pragma unroll
            for (int i = 0; i < 4; i++) acc[mt][nt][i] = 0.f;

    uint32_t aAddr[4], bAddr[4];
    {
        int ar = warpM * 64 + ((lane >> 3) & 1) * 8 + (lane & 7);
        int ac = ((lane >> 4) & 1) * 4;
#pragma unroll
        for (int mt = 0; mt < 4; mt++)
            aAddr[mt] = (uint32_t)__cvta_generic_to_shared(&As[ar + mt * 16][ac]);
        int br = warpN * 32 + (lane & 7);
        int bc = ((lane >> 3) & 1) * 4;
#pragma unroll
        for (int nt = 0; nt < 4; nt++)
            bAddr[nt] = (uint32_t)__cvta_generic_to_shared(&Bt[br + nt * 8][bc]);
    }

    float4 pa[4], pb[4];
    const int a_row = tid >> 3;
    const int a_c4  = (tid & 7) * 4;

#define LOADCHUNK1(KC0)                                                        \
    {                                                                          \
        _Pragma("unroll")                                                      \
        for (int i = 0; i < 4; i++) {                                          \
            int row = a_row + i * 32;                                          \
            int grow = min(rowBase + row, M - 1);                              \
            pa[i] = *(const float4*)&A[(size_t)grow * DD + (KC0) + a_c4];      \
        }                                                                      \
        _Pragma("unroll")                                                      \
        for (int i = 0; i < 4; i++) {                                          \
            int lin = tid + i * 256;                                           \
            int kr = lin >> 5;                                                 \
            int n4 = (lin & 31) * 4;                                           \
            pb[i] = *(const float4*)&B[(size_t)((KC0) + kr) * DD + n4];        \
        }                                                                      \
    }

#define STORECHUNK1()                                                          \
    {                                                                          \
        _Pragma("unroll")                                                      \
        for (int i = 0; i < 4; i++) {                                          \
            int row = a_row + i * 32;                                          \
            *(uint4*)&As[row][a_c4] = make_uint4(                              \
                f2tf32(pa[i].x), f2tf32(pa[i].y), f2tf32(pa[i].z), f2tf32(pa[i].w)); \
        }                                                                      \
        _Pragma("unroll")                                                      \
        for (int i = 0; i < 4; i++) {                                          \
            int lin = tid + i * 256;                                           \
            int kr = lin >> 5;                                                 \
            int n4 = (lin & 31) * 4;                                           \
            Bt[n4 + 0][kr] = f2tf32(pb[i].x);                                  \
            Bt[n4 + 1][kr] = f2tf32(pb[i].y);                                  \
            Bt[n4 + 2][kr] = f2tf32(pb[i].z);                                  \
            Bt[n4 + 3][kr] = f2tf32(pb[i].w);                                  \
        }                                                                      \
    }

    LOADCHUNK1(0);
    STORECHUNK1();
    __syncthreads();

    for (int kc = 0; kc < 4; kc++) {
        if (kc < 3) LOADCHUNK1((kc + 1) * 32);
#pragma unroll
        for (int ks = 0; ks < 4; ks++) {
            uint32_t a[4][4], b[4][2];
#pragma unroll
            for (int nt = 0; nt < 4; nt++) {
                asm volatile("ldmatrix.sync.aligned.m8n8.x2.shared.b16 {%0,%1}, [%2];"
                             : "=r"(b[nt][0]), "=r"(b[nt][1])
                             : "r"(bAddr[nt] + ks * 32));
            }
#pragma unroll
            for (int mt = 0; mt < 4; mt++) {
                asm volatile("ldmatrix.sync.aligned.m8n8.x4.shared.b16 {%0,%1,%2,%3}, [%4];"
                             : "=r"(a[mt][0]), "=r"(a[mt][1]), "=r"(a[mt][2]), "=r"(a[mt][3])
                             : "r"(aAddr[mt] + ks * 32));
            }
#pragma unroll
            for (int mt = 0; mt < 4; mt++)
#pragma unroll
                for (int nt = 0; nt < 4; nt++) {
                    asm volatile(
                        "mma.sync.aligned.m16n8k8.row.col.f32.tf32.tf32.f32 "
                        "{%0,%1,%2,%3}, {%4,%5,%6,%7}, {%8,%9}, {%0,%1,%2,%3};"
                        : "+f"(acc[mt][nt][0]), "+f"(acc[mt][nt][1]),
                          "+f"(acc[mt][nt][2]), "+f"(acc[mt][nt][3])
                        : "r"(a[mt][0]), "r"(a[mt][1]), "r"(a[mt][2]), "r"(a[mt][3]),
                          "r"(b[nt][0]), "r"(b[nt][1]));
                }
        }
        __syncthreads();
        if (kc < 3) {
            STORECHUNK1();
            __syncthreads();
        }
    }

    const int g = lane >> 2;
    const int t = lane & 3;
#pragma unroll
    for (int mt = 0; mt < 4; mt++) {
        int r0 = rowBase + warpM * 64 + mt * 16 + g;
#pragma unroll
        for (int nt = 0; nt < 4; nt++) {
            int col = warpN * 32 + nt * 8 + t * 2;
            float2 v0 = make_float2(acc[mt][nt][0], acc[mt][nt][1]);
            float2 v1 = make_float2(acc[mt][nt][2], acc[mt][nt][3]);
            if (HALFOUT) {
                if (r0 < M)     *(__half2*)&g_Hh[(size_t)r0 * DD + col] = __floats2half2_rn(v0.x, v0.y);
                if (r0 + 8 < M) *(__half2*)&g_Hh[(size_t)(r0 + 8) * DD + col] = __floats2half2_rn(v1.x, v1.y);
            } else {
                if (BIAS) {
                    float2 bv = *(const float2*)&bias[col];
                    v0.x += bv.x; v0.y += bv.y;
                    v1.x += bv.x; v1.y += bv.y;
                }
                if (r0 < M)     *(float2*)&Cext[(size_t)r0 * DD + col] = v0;
                if (r0 + 8 < M) *(float2*)&Cext[(size_t)(r0 + 8) * DD + col] = v1;
            }
        }
    }
#undef LOADCHUNK1
#undef STORECHUNK1
}

// ---------------- CSR gather-aggregate, 2 edges/iter ----------------
// One warp per node. Each lane loads uint4 (8 halves, 16B); lanes 0-15 cover
// even edges, lanes 16-31 odd edges. shfl_xor(16) merges; lanes 0-15 finish.
template <int RESID, int DSTID, bool RELU>
__global__ void __launch_bounds__(256) k_aggregate()
{
    int node = (blockIdx.x * blockDim.x + threadIdx.x) >> 5;
    if (node >= NN) return;
    int lane = threadIdx.x & 31;
    int colBase = (lane & 15) * 8;       // 8 halves per lane

    float acc[8];
#pragma unroll
    for (int i = 0; i < 8; i++) acc[i] = 0.f;

    int s = g_off[node];
    int end = s + g_cnt[node];

    for (int j = s + (lane >> 4); j < end; j += 2) {
        int r = g_csr_row[j];
        float w = g_csr_nrm[j];
        uint4 u = *(const uint4*)&g_Hh[(size_t)r * DD + colBase];
        float2 f0 = __half22float2(*(__half2*)&u.x);
        float2 f1 = __half22float2(((__half2*)&u.x)[1]);
        float2 f2 = __half22float2(*(__half2*)&u.z);
        float2 f3 = __half22float2(((__half2*)&u.z)[1]);
        acc[0] += f0.x * w; acc[1] += f0.y * w;
        acc[2] += f1.x * w; acc[3] += f1.y * w;
        acc[4] += f2.x * w; acc[5] += f2.y * w;
        acc[6] += f3.x * w; acc[7] += f3.y * w;
    }

    // merge even/odd half-warp partials
#pragma unroll
    for (int i = 0; i < 8; i++)
        acc[i] += __shfl_xor_sync(0xffffffffu, acc[i], 16);

    if (lane < 16) {
        // self loop
        float d = g_dinv[node];
        float d2 = d * d;
        uint4 u = *(const uint4*)&g_Hh[(size_t)node * DD + colBase];
        float2 f0 = __half22float2(*(__half2*)&u.x);
        float2 f1 = __half22float2(((__half2*)&u.x)[1]);
        float2 f2 = __half22float2(*(__half2*)&u.z);
        float2 f3 = __half22float2(((__half2*)&u.z)[1]);
        acc[0] += f0.x * d2; acc[1] += f0.y * d2;
        acc[2] += f1.x * d2; acc[3] += f1.y * d2;
        acc[4] += f2.x * d2; acc[5] += f2.y * d2;
        acc[6] += f3.x * d2; acc[7] += f3.y * d2;

        if (RESID >= 0) {
            const float* R = (const float*)g_buf[RESID < 0 ? 0 : RESID];
            float4 r0 = *(const float4*)&R[(size_t)node * DD + colBase];
            float4 r1 = *(const float4*)&R[(size_t)node * DD + colBase + 4];
            acc[0] += r0.x; acc[1] += r0.y; acc[2] += r0.z; acc[3] += r0.w;
            acc[4] += r1.x; acc[5] += r1.y; acc[6] += r1.z; acc[7] += r1.w;
        }
        if (RELU) {
#pragma unroll
            for (int i = 0; i < 8; i++) acc[i] = fmaxf(acc[i], 0.f);
        }
        float* D = (float*)g_buf[DSTID];
        *(float4*)&D[(size_t)node * DD + colBase]     = make_float4(acc[0], acc[1], acc[2], acc[3]);
        *(float4*)&D[(size_t)node * DD + colBase + 4] = make_float4(acc[4], acc[5], acc[6], acc[7]);
    }
}

extern "C" void kernel_launch(void* const* d_in, const int* in_sizes, int n_in,
                              void* d_out, int out_size)
{
    const float* x  = (const float*)d_in[0];
    const void*  ei = d_in[1];
    const float* W1 = (const float*)d_in[2];
    const float* R1 = (const float*)d_in[3];
    const float* W2 = (const float*)d_in[4];
    const float* R2 = (const float*)d_in[5];
    const float* W3 = (const float*)d_in[6];
    const float* Wh = (const float*)d_in[7];
    const float* bh = (const float*)d_in[8];
    float* out = (float*)d_out;

    const int GEMM_GRID = (NN + 127) / 128;
    const int AGG_GRID  = (NN * 32 + 255) / 256;
    const int E_GRID    = (EE + 255) / 256;
    const int N_GRID    = (NN + 255) / 256;

    // ---- CSR prep ----
    k_init<<<N_GRID, 256>>>(ei);
    k_count<<<E_GRID, 256>>>(ei);
    k_scan1<<<NBLK, 256>>>();
    k_scan2<<<1, 256>>>();
    k_scan3<<<NBLK, 256>>>();
    k_fill<<<E_GRID, 256>>>();

    // ---- layer 1 ----
    k_gemm2<-1, 0><<<GEMM_GRID, 512>>>(x, W1, R1, NN);
    k_aggregate<0, 1, true><<<AGG_GRID, 256>>>();

    // ---- layer 2 ----
    k_gemm2<1, 0><<<GEMM_GRID, 512>>>(nullptr, W2, R2, NN);
    k_aggregate<0, 1, true><<<AGG_GRID, 256>>>();

    // ---- layer 3 ----
    k_gemm<1, true, false><<<GEMM_GRID, 256>>>(nullptr, W3, nullptr, nullptr, NN);
    k_aggregate<-1, 0, false><<<AGG_GRID, 256>>>();

    // ---- head ----
    k_gemm<0, false, true><<<GEMM_GRID, 256>>>(nullptr, Wh, bh, out, NN);
}